// round 10
// baseline (speedup 1.0000x reference)
#include <cuda_runtime.h>
#include <cuda_bf16.h>
#include <math.h>

#define Bc      8
#define Nc      1024
#define Mc      512
#define Dc      128
#define Lc      6
#define DFFc    512
#define Sc      1536
#define HDc     16
#define MAXNB   64
#define ROWS    12288
#define PER_L   196608

// ---------------- scratch ------------------------------------------------------
__device__ float g_x  [ROWS * Dc];
__device__ float g_qkv[ROWS * 384];
__device__ float g_te [Bc * Dc];
__device__ float g_nodes[ROWS];
__device__ int   g_adj[Sc * MAXNB];
__device__ int   g_adjcnt[Sc];

__device__ __nv_bfloat16 g_wThi[Lc * PER_L];
__device__ __nv_bfloat16 g_wTlo[Lc * PER_L];
__device__ __nv_bfloat16 g_ohi[ROWS * Dc];
__device__ __nv_bfloat16 g_olo[ROWS * Dc];
__device__ __nv_bfloat16 g_fhi[ROWS * DFFc];
__device__ __nv_bfloat16 g_flo[ROWS * DFFc];

__device__ __forceinline__ void split_bf16(float v, __nv_bfloat16& hi, __nv_bfloat16& lo) {
    hi = __float2bfloat16_rn(v);
    lo = __float2bfloat16_rn(v - __bfloat162float(hi));
}
__device__ __forceinline__ unsigned pack2hi(float a, float b) {
    __nv_bfloat162 p; p.x = __float2bfloat16_rn(a); p.y = __float2bfloat16_rn(b);
    return *(unsigned*)&p;
}
__device__ __forceinline__ unsigned pack2lo(float a, float b) {
    __nv_bfloat162 p;
    p.x = __float2bfloat16_rn(a - __bfloat162float(__float2bfloat16_rn(a)));
    p.y = __float2bfloat16_rn(b - __bfloat162float(__float2bfloat16_rn(b)));
    return *(unsigned*)&p;
}

// ---------------- merged init: te + syndrome nodes + adjacency ------------------
__global__ void k_init0(const int* __restrict__ t, const float* __restrict__ time_table,
                        const float* __restrict__ r_t, const int* __restrict__ pcm) {
    int blk = blockIdx.x;
    int lane = threadIdx.x & 31;
    if (blk < 512) {
        int w = blk * 8 + (threadIdx.x >> 5);
        int b = w >> 9, m = w & 511;
        int cnt = 0;
        #pragma unroll
        for (int i = 0; i < 32; i++) {
            int col = lane + i * 32;
            bool pred = (pcm[(size_t)m * Nc + col] != 0) && (r_t[(size_t)b * Nc + col] < 0.0f);
            cnt += __popc(__ballot_sync(0xffffffffu, pred));
        }
        if (lane == 0) g_nodes[(size_t)b * Sc + Nc + m] = (float)(cnt & 1);
    } else if (blk < 704) {
        int s = (blk - 512) * 8 + (threadIdx.x >> 5);
        unsigned lt = (1u << lane) - 1u;
        int* adj = g_adj + s * MAXNB;
        int cnt = 1;
        if (lane == 0) adj[0] = s;
        if (s < Nc) {
            #pragma unroll
            for (int i = 0; i < 16; i++) {
                int m = lane + i * 32;
                bool pred = pcm[(size_t)m * Nc + s] != 0;
                unsigned bal = __ballot_sync(0xffffffffu, pred);
                int rank = __popc(bal & lt);
                if (pred && cnt + rank < MAXNB) adj[cnt + rank] = Nc + m;
                cnt += __popc(bal);
            }
        } else {
            const int* row = pcm + (size_t)(s - Nc) * Nc;
            #pragma unroll
            for (int i = 0; i < 32; i++) {
                int n = lane + i * 32;
                bool pred = row[n] != 0;
                unsigned bal = __ballot_sync(0xffffffffu, pred);
                int rank = __popc(bal & lt);
                if (pred && cnt + rank < MAXNB) adj[cnt + rank] = n;
                cnt += __popc(bal);
            }
        }
        if (lane == 0) g_adjcnt[s] = cnt < MAXNB ? cnt : MAXNB;
    } else {
        #pragma unroll
        for (int i = threadIdx.x; i < Bc * Dc; i += 256) {
            int b = i >> 7, d = i & 127;
            g_te[i] = time_table[t[b] * Dc + d];
        }
    }
}

__global__ void k_xinit(const float* __restrict__ src_embed, const float* __restrict__ r_t) {
    int i = blockIdx.x * blockDim.x + threadIdx.x;
    if (i >= ROWS * Dc) return;
    int d = i & 127;
    int bs = i >> 7;
    int b = bs / Sc, s = bs % Sc;
    float node = (s < Nc) ? fabsf(r_t[(size_t)b * Nc + s]) : g_nodes[bs];
    g_x[i] = src_embed[s * Dc + d] * node * g_te[b * Dc + d];
}

// ---------------- weight transpose+split ----------------------------------------
__global__ void k_wsplit(const float* __restrict__ Wq, const float* __restrict__ Wk,
                         const float* __restrict__ Wv, const float* __restrict__ Wo,
                         const float* __restrict__ W1, const float* __restrict__ W2) {
    __shared__ float s[32][33];
    int bid = blockIdx.x;
    int l = bid / 192, tt = bid % 192;
    const float* src; int Nn, k0, n0; size_t dstBase; int dstLd;
    if (tt < 64) {
        int seg = tt >> 4, local = tt & 15;
        k0 = (local >> 2) * 32; n0 = (local & 3) * 32; Nn = 128; dstLd = 128;
        if      (seg == 0) { src = Wq + (size_t)l * 16384; dstBase = (size_t)l * PER_L; }
        else if (seg == 1) { src = Wk + (size_t)l * 16384; dstBase = (size_t)l * PER_L + 16384; }
        else if (seg == 2) { src = Wv + (size_t)l * 16384; dstBase = (size_t)l * PER_L + 32768; }
        else               { src = Wo + (size_t)l * 16384; dstBase = (size_t)l * PER_L + 49152; }
    } else if (tt < 128) {
        int local = tt - 64;
        k0 = (local >> 4) * 32; n0 = (local & 15) * 32; Nn = 512; dstLd = 128;
        src = W1 + (size_t)l * 65536; dstBase = (size_t)l * PER_L + 65536;
    } else {
        int local = tt - 128;
        k0 = (local >> 2) * 32; n0 = (local & 3) * 32; Nn = 128; dstLd = 512;
        src = W2 + (size_t)l * 65536; dstBase = (size_t)l * PER_L + 131072;
    }
    int tx = threadIdx.x & 31, ty = threadIdx.x >> 5;
    #pragma unroll
    for (int j = 0; j < 4; j++)
        s[ty + j * 8][tx] = src[(size_t)(k0 + ty + j * 8) * Nn + n0 + tx];
    __syncthreads();
    #pragma unroll
    for (int j = 0; j < 4; j++) {
        int n = n0 + ty + j * 8;
        float v = s[tx][ty + j * 8];
        __nv_bfloat16 hi, lo;
        split_bf16(v, hi, lo);
        size_t o = dstBase + (size_t)n * dstLd + k0 + tx;
        g_wThi[o] = hi;
        g_wTlo[o] = lo;
    }
}

// ---------------- fused LN + bf16x3 GEMM, ldmatrix inner loop --------------------
#define SW 68
#define A_WORDS (128 * SW)
#define B_WORDS (64 * SW)
#define SMEMB ((2 * A_WORDS + 2 * B_WORDS) * 4)
#define ROWS16B (16 * SW * 4)

__device__ __forceinline__ void mma_bf16(float* c, const unsigned* a, const unsigned* b) {
    asm volatile(
        "mma.sync.aligned.m16n8k16.row.col.f32.bf16.bf16.f32 "
        "{%0,%1,%2,%3}, {%4,%5,%6,%7}, {%8,%9}, {%0,%1,%2,%3};"
        : "+f"(c[0]), "+f"(c[1]), "+f"(c[2]), "+f"(c[3])
        : "r"(a[0]), "r"(a[1]), "r"(a[2]), "r"(a[3]), "r"(b[0]), "r"(b[1]));
}
__device__ __forceinline__ void ldsm4(unsigned* d, unsigned addr) {
    asm volatile("ldmatrix.sync.aligned.m8n8.x4.shared.b16 {%0,%1,%2,%3}, [%4];"
                 : "=r"(d[0]), "=r"(d[1]), "=r"(d[2]), "=r"(d[3]) : "r"(addr));
}

template <int AMODE, int EPI, int NT>   // BN = 16*NT
__global__ void __launch_bounds__(256)
k_gemm(const float* __restrict__ Xf,
       const __nv_bfloat16* __restrict__ Ahi, const __nv_bfloat16* __restrict__ Alo,
       const float* __restrict__ gg, const float* __restrict__ bb,
       const __nv_bfloat16* __restrict__ Bhi, const __nv_bfloat16* __restrict__ Blo,
       float* __restrict__ C, __nv_bfloat16* __restrict__ Chi, __nv_bfloat16* __restrict__ Clo,
       int K, int Nn) {
    extern __shared__ unsigned smw[];
    unsigned* sAhi = smw;
    unsigned* sAlo = sAhi + A_WORDS;
    unsigned* sBhi = sAlo + A_WORDS;
    unsigned* sBlo = sBhi + B_WORDS;

    const int tid = threadIdx.x;
    const int lane = tid & 31, warp = tid >> 5;
    const int wm = (warp >> 1) * 32, wn = (warp & 1) * (NT * 8);
    const int g = lane >> 2, q4 = lane & 3;
    const int BN = 16 * NT;
    const int rowBase = blockIdx.y * 128, colBase = blockIdx.x * BN;

    const unsigned aOff = (unsigned)((wm + (lane & 15)) * SW + (lane >> 4) * 4) * 4u;
    const unsigned bOff = (unsigned)((wn + ((lane >> 4) & 1) * 8 + (lane & 7)) * SW
                                     + ((lane >> 3) & 1) * 4) * 4u;
    const unsigned aHiBase = (unsigned)__cvta_generic_to_shared(sAhi) + aOff;
    const unsigned aLoBase = (unsigned)__cvta_generic_to_shared(sAlo) + aOff;
    const unsigned bHiBase = (unsigned)__cvta_generic_to_shared(sBhi) + bOff;
    const unsigned bLoBase = (unsigned)__cvta_generic_to_shared(sBlo) + bOff;

    float acc[2][NT][4];
    #pragma unroll
    for (int mt = 0; mt < 2; mt++)
        #pragma unroll
        for (int nt = 0; nt < NT; nt++)
            #pragma unroll
            for (int i = 0; i < 4; i++) acc[mt][nt][i] = 0.0f;

    for (int kt = 0; kt < K; kt += 128) {
        if (kt) __syncthreads();
        // ---- A slice ----
        if (AMODE == 0) {
            #pragma unroll
            for (int i = 0; i < 8; i++) {
                int t = tid + i * 256;
                int r = t >> 4, c = t & 15;
                size_t goff = (size_t)(rowBase + r) * K + kt + c * 8;
                *(uint4*)&sAhi[r * SW + c * 4] = *(const uint4*)(Ahi + goff);
                *(uint4*)&sAlo[r * SW + c * 4] = *(const uint4*)(Alo + goff);
            }
        } else {
            // fused LayerNorm, cheap-reduction form:
            // thread = 16 contiguous cols of one row; 8-lane butterfly (3 stages).
            const int c0 = (tid & 7) * 16;      // column start
            const int w0 = (tid & 7) * 8;       // word start within smem row
            const int bIdx = rowBase / Sc;
            #pragma unroll
            for (int pass = 0; pass < 4; pass++) {
                int r = pass * 32 + (tid >> 3);
                const float* xr = &Xf[(size_t)(rowBase + r) * 128 + c0];
                float4 x0 = *(const float4*)(xr + 0);
                float4 x1 = *(const float4*)(xr + 4);
                float4 x2 = *(const float4*)(xr + 8);
                float4 x3 = *(const float4*)(xr + 12);
                float s1 = (x0.x + x0.y + x0.z + x0.w) + (x1.x + x1.y + x1.z + x1.w)
                         + (x2.x + x2.y + x2.z + x2.w) + (x3.x + x3.y + x3.z + x3.w);
                float s2 = x0.x * x0.x;
                s2 = fmaf(x0.y, x0.y, s2); s2 = fmaf(x0.z, x0.z, s2); s2 = fmaf(x0.w, x0.w, s2);
                s2 = fmaf(x1.x, x1.x, s2); s2 = fmaf(x1.y, x1.y, s2);
                s2 = fmaf(x1.z, x1.z, s2); s2 = fmaf(x1.w, x1.w, s2);
                s2 = fmaf(x2.x, x2.x, s2); s2 = fmaf(x2.y, x2.y, s2);
                s2 = fmaf(x2.z, x2.z, s2); s2 = fmaf(x2.w, x2.w, s2);
                s2 = fmaf(x3.x, x3.x, s2); s2 = fmaf(x3.y, x3.y, s2);
                s2 = fmaf(x3.z, x3.z, s2); s2 = fmaf(x3.w, x3.w, s2);
                #pragma unroll
                for (int o = 4; o > 0; o >>= 1) {
                    s1 += __shfl_xor_sync(0xffffffffu, s1, o);
                    s2 += __shfl_xor_sync(0xffffffffu, s2, o);
                }
                float mean = s1 * (1.0f / 128.0f);
                float var  = s2 * (1.0f / 128.0f) - mean * mean;
                float inv  = rsqrtf(var + 1e-5f);

                float xv[16] = {x0.x, x0.y, x0.z, x0.w, x1.x, x1.y, x1.z, x1.w,
                                x2.x, x2.y, x2.z, x2.w, x3.x, x3.y, x3.z, x3.w};
                float ov[16];
                #pragma unroll
                for (int j = 0; j < 4; j++) {
                    float4 gj = *(const float4*)&gg[c0 + j * 4];
                    float4 bj = *(const float4*)&bb[c0 + j * 4];
                    ov[j * 4 + 0] = (xv[j * 4 + 0] - mean) * inv * gj.x + bj.x;
                    ov[j * 4 + 1] = (xv[j * 4 + 1] - mean) * inv * gj.y + bj.y;
                    ov[j * 4 + 2] = (xv[j * 4 + 2] - mean) * inv * gj.z + bj.z;
                    ov[j * 4 + 3] = (xv[j * 4 + 3] - mean) * inv * gj.w + bj.w;
                    if (AMODE == 2) {
                        float4 tj = *(const float4*)&g_te[bIdx * Dc + c0 + j * 4];
                        ov[j * 4 + 0] *= tj.x; ov[j * 4 + 1] *= tj.y;
                        ov[j * 4 + 2] *= tj.z; ov[j * 4 + 3] *= tj.w;
                    }
                }
                uint4 h0 = make_uint4(pack2hi(ov[0], ov[1]),  pack2hi(ov[2], ov[3]),
                                      pack2hi(ov[4], ov[5]),  pack2hi(ov[6], ov[7]));
                uint4 h1 = make_uint4(pack2hi(ov[8], ov[9]),  pack2hi(ov[10], ov[11]),
                                      pack2hi(ov[12], ov[13]), pack2hi(ov[14], ov[15]));
                uint4 l0 = make_uint4(pack2lo(ov[0], ov[1]),  pack2lo(ov[2], ov[3]),
                                      pack2lo(ov[4], ov[5]),  pack2lo(ov[6], ov[7]));
                uint4 l1 = make_uint4(pack2lo(ov[8], ov[9]),  pack2lo(ov[10], ov[11]),
                                      pack2lo(ov[12], ov[13]), pack2lo(ov[14], ov[15]));
                *(uint4*)&sAhi[r * SW + w0]     = h0;
                *(uint4*)&sAhi[r * SW + w0 + 4] = h1;
                *(uint4*)&sAlo[r * SW + w0]     = l0;
                *(uint4*)&sAlo[r * SW + w0 + 4] = l1;
            }
        }
        // ---- B slice ----
        #pragma unroll
        for (int i = 0; i < NT; i++) {
            int t = tid + i * 256;
            int n = t >> 4, c = t & 15;
            size_t goff = (size_t)(colBase + n) * K + kt + c * 8;
            *(uint4*)&sBhi[n * SW + c * 4] = *(const uint4*)(Bhi + goff);
            *(uint4*)&sBlo[n * SW + c * 4] = *(const uint4*)(Blo + goff);
        }
        __syncthreads();

        #pragma unroll
        for (int ks = 0; ks < 8; ks++) {
            const unsigned ko = ks * 32u;
            unsigned ah[2][4], al[2][4], bh[NT][2], bl[NT][2];
            #pragma unroll
            for (int mt = 0; mt < 2; mt++) {
                ldsm4(ah[mt], aHiBase + mt * ROWS16B + ko);
                ldsm4(al[mt], aLoBase + mt * ROWS16B + ko);
            }
            #pragma unroll
            for (int pr = 0; pr < NT / 2; pr++) {
                unsigned t0[4], t1[4];
                ldsm4(t0, bHiBase + pr * ROWS16B + ko);
                ldsm4(t1, bLoBase + pr * ROWS16B + ko);
                bh[pr * 2][0] = t0[0]; bh[pr * 2][1] = t0[1];
                bh[pr * 2 + 1][0] = t0[2]; bh[pr * 2 + 1][1] = t0[3];
                bl[pr * 2][0] = t1[0]; bl[pr * 2][1] = t1[1];
                bl[pr * 2 + 1][0] = t1[2]; bl[pr * 2 + 1][1] = t1[3];
            }
            #pragma unroll
            for (int mt = 0; mt < 2; mt++)
                #pragma unroll
                for (int nt = 0; nt < NT; nt++) {
                    mma_bf16(acc[mt][nt], ah[mt], bh[nt]);
                    mma_bf16(acc[mt][nt], ah[mt], bl[nt]);
                    mma_bf16(acc[mt][nt], al[mt], bh[nt]);
                }
        }
    }

    // ---- epilogue ----
    #pragma unroll
    for (int mt = 0; mt < 2; mt++)
        #pragma unroll
        for (int nt = 0; nt < NT; nt++) {
            int r = rowBase + wm + mt * 16 + g;
            int c = colBase + wn + nt * 8 + q4 * 2;
            float* a = acc[mt][nt];
            if (EPI == 0) {
                *(float2*)&C[(size_t)r * Nn + c]       = make_float2(a[0], a[1]);
                *(float2*)&C[(size_t)(r + 8) * Nn + c] = make_float2(a[2], a[3]);
            } else if (EPI == 1) {
                float2 v0 = *(const float2*)&C[(size_t)r * Nn + c];
                float2 v1 = *(const float2*)&C[(size_t)(r + 8) * Nn + c];
                v0.x += a[0]; v0.y += a[1]; v1.x += a[2]; v1.y += a[3];
                *(float2*)&C[(size_t)r * Nn + c]       = v0;
                *(float2*)&C[(size_t)(r + 8) * Nn + c] = v1;
            } else {
                #pragma unroll
                for (int rr = 0; rr < 2; rr++) {
                    float v0 = fmaxf(a[rr * 2 + 0], 0.0f);
                    float v1 = fmaxf(a[rr * 2 + 1], 0.0f);
                    size_t o = (size_t)(r + rr * 8) * Nn + c;
                    *(unsigned*)&Chi[o] = pack2hi(v0, v1);
                    *(unsigned*)&Clo[o] = pack2lo(v0, v1);
                }
            }
        }
}

// ---------------- sparse attention: warp per row, online softmax -----------------
__global__ void __launch_bounds__(256)
k_attn(const float* __restrict__ qkv,
       __nv_bfloat16* __restrict__ ohi, __nv_bfloat16* __restrict__ olo) {
    int warp = threadIdx.x >> 5, lane = threadIdx.x & 31;
    int bs = blockIdx.x * 8 + warp;
    int b = bs / Sc, s = bs % Sc;
    int cnt = g_adjcnt[s];
    const int* adj = g_adj + s * MAXNB;

    float4 qv = *(const float4*)&qkv[(size_t)bs * 384 + lane * 4];

    float m = -1e30f, l = 0.0f;
    float4 acc = make_float4(0.0f, 0.0f, 0.0f, 0.0f);

    for (int j = 0; j < cnt; j++) {
        int n = adj[j];
        const float* kr = qkv + ((size_t)b * Sc + n) * 384 + 128;
        float4 kv = *(const float4*)&kr[lane * 4];
        float d = qv.x * kv.x + qv.y * kv.y + qv.z * kv.z + qv.w * kv.w;
        d += __shfl_xor_sync(0xffffffffu, d, 1);
        d += __shfl_xor_sync(0xffffffffu, d, 2);
        float sc = d * 0.25f;
        float mn = fmaxf(m, sc);
        float scale = __expf(m - mn);
        float p = __expf(sc - mn);
        l = l * scale + p;
        float4 vv = *(const float4*)&kr[128 + lane * 4];
        acc.x = acc.x * scale + p * vv.x;
        acc.y = acc.y * scale + p * vv.y;
        acc.z = acc.z * scale + p * vv.z;
        acc.w = acc.w * scale + p * vv.w;
        m = mn;
    }

    float inv = 1.0f / l;
    float v0 = acc.x * inv, v1 = acc.y * inv, v2 = acc.z * inv, v3 = acc.w * inv;
    size_t o = (size_t)bs * Dc + lane * 4;
    *(unsigned*)&ohi[o]     = pack2hi(v0, v1);
    *(unsigned*)&ohi[o + 2] = pack2hi(v2, v3);
    *(unsigned*)&olo[o]     = pack2lo(v0, v1);
    *(unsigned*)&olo[o + 2] = pack2lo(v2, v3);
}

// ---------------- final projection -----------------------------------------------
__global__ void k_out(const float* __restrict__ fc_w, const float* __restrict__ fc_b,
                      float* __restrict__ out) {
    int row = blockIdx.x * 8 + (threadIdx.x >> 5);
    if (row >= ROWS) return;
    int lane = threadIdx.x & 31;
    float sum = 0.0f;
    #pragma unroll
    for (int d = lane; d < Dc; d += 32) sum += g_x[(size_t)row * Dc + d] * fc_w[d];
    #pragma unroll
    for (int off = 16; off > 0; off >>= 1) sum += __shfl_xor_sync(0xffffffffu, sum, off);
    if (lane == 0) out[row] = sum + fc_b[0];
}

// ---------------- launcher ---------------------------------------------------------
extern "C" void kernel_launch(void* const* d_in, const int* in_sizes, int n_in,
                              void* d_out, int out_size) {
    const float* r_t        = (const float*)d_in[0];
    const int*   t          = (const int*)  d_in[1];
    const int*   pcm        = (const int*)  d_in[2];
    const float* src_embed  = (const float*)d_in[4];
    const float* time_table = (const float*)d_in[5];
    const float* Wq = (const float*)d_in[6];
    const float* Wk = (const float*)d_in[7];
    const float* Wv = (const float*)d_in[8];
    const float* Wo = (const float*)d_in[9];
    const float* W1 = (const float*)d_in[10];
    const float* W2 = (const float*)d_in[11];
    const float* g1 = (const float*)d_in[12];
    const float* b1 = (const float*)d_in[13];
    const float* g2 = (const float*)d_in[14];
    const float* b2 = (const float*)d_in[15];
    const float* fc_w = (const float*)d_in[16];
    const float* fc_b = (const float*)d_in[17];
    float* out = (float*)d_out;

    float *px, *pqkv;
    __nv_bfloat16 *whi, *wlo, *ohi, *olo, *fhi, *flo;
    cudaGetSymbolAddress((void**)&px,   g_x);
    cudaGetSymbolAddress((void**)&pqkv, g_qkv);
    cudaGetSymbolAddress((void**)&whi,  g_wThi);
    cudaGetSymbolAddress((void**)&wlo,  g_wTlo);
    cudaGetSymbolAddress((void**)&ohi,  g_ohi);
    cudaGetSymbolAddress((void**)&olo,  g_olo);
    cudaGetSymbolAddress((void**)&fhi,  g_fhi);
    cudaGetSymbolAddress((void**)&flo,  g_flo);

    static int smemSet = 0;
    if (!smemSet) {
        cudaFuncSetAttribute(k_gemm<1,0,4>, cudaFuncAttributeMaxDynamicSharedMemorySize, SMEMB);
        cudaFuncSetAttribute(k_gemm<0,1,2>, cudaFuncAttributeMaxDynamicSharedMemorySize, SMEMB);
        cudaFuncSetAttribute(k_gemm<2,2,4>, cudaFuncAttributeMaxDynamicSharedMemorySize, SMEMB);
        smemSet = 1;
    }

    k_init0<<<705, 256>>>(t, time_table, r_t, pcm);
    k_xinit<<<(ROWS * Dc + 255) / 256, 256>>>(src_embed, r_t);
    k_wsplit<<<Lc * 192, 256>>>(Wq, Wk, Wv, Wo, W1, W2);

    dim3 gQKV(6, 96);    // BN=64
    dim3 gD32(4, 96);    // BN=32 (384 CTAs)
    dim3 gF  (8, 96);    // BN=64

    for (int l = 0; l < Lc; l++) {
        const __nv_bfloat16* lwh = whi + (size_t)l * PER_L;
        const __nv_bfloat16* lwl = wlo + (size_t)l * PER_L;

        k_gemm<1,0,4><<<gQKV, 256, SMEMB>>>(px, nullptr, nullptr, g1 + l * Dc, b1 + l * Dc,
                                            lwh, lwl, pqkv, nullptr, nullptr, 128, 384);
        k_attn<<<ROWS / 8, 256>>>(pqkv, ohi, olo);
        k_gemm<0,1,2><<<gD32, 256, SMEMB>>>(nullptr, ohi, olo, nullptr, nullptr,
                                            lwh + 49152, lwl + 49152, px, nullptr, nullptr, 128, 128);
        k_gemm<2,2,4><<<gF, 256, SMEMB>>>(px, nullptr, nullptr, g2 + l * Dc, b2 + l * Dc,
                                          lwh + 65536, lwl + 65536, nullptr, fhi, flo, 128, 512);
        k_gemm<0,1,2><<<gD32, 256, SMEMB>>>(nullptr, fhi, flo, nullptr, nullptr,
                                            lwh + 131072, lwl + 131072, px, nullptr, nullptr, 512, 128);
    }

    k_out<<<(ROWS + 7) / 8, 256>>>(fc_w, fc_b, out);
}

// round 12
// speedup vs baseline: 1.2182x; 1.2182x over previous
#include <cuda_runtime.h>
#include <cuda_bf16.h>
#include <math.h>

#define Bc      8
#define Nc      1024
#define Mc      512
#define Dc      128
#define Lc      6
#define DFFc    512
#define Sc      1536
#define HDc     16
#define MAXNB   64
#define ROWS    12288
#define PER_L   196608

// ---------------- scratch ------------------------------------------------------
__device__ float g_x  [ROWS * Dc];
__device__ float g_qkv[ROWS * 384];
__device__ float g_te [Bc * Dc];
__device__ float g_nodes[ROWS];
__device__ int   g_adj[Sc * MAXNB];
__device__ int   g_adjcnt[Sc];

__device__ __nv_bfloat16 g_wThi[Lc * PER_L];
__device__ __nv_bfloat16 g_wTlo[Lc * PER_L];
__device__ __nv_bfloat16 g_ohi[ROWS * Dc];
__device__ __nv_bfloat16 g_olo[ROWS * Dc];
__device__ __nv_bfloat16 g_fhi[ROWS * DFFc];
__device__ __nv_bfloat16 g_flo[ROWS * DFFc];

__device__ __forceinline__ void split_bf16(float v, __nv_bfloat16& hi, __nv_bfloat16& lo) {
    hi = __float2bfloat16_rn(v);
    lo = __float2bfloat16_rn(v - __bfloat162float(hi));
}
__device__ __forceinline__ unsigned pack2hi(float a, float b) {
    __nv_bfloat162 p; p.x = __float2bfloat16_rn(a); p.y = __float2bfloat16_rn(b);
    return *(unsigned*)&p;
}
__device__ __forceinline__ unsigned pack2lo(float a, float b) {
    __nv_bfloat162 p;
    p.x = __float2bfloat16_rn(a - __bfloat162float(__float2bfloat16_rn(a)));
    p.y = __float2bfloat16_rn(b - __bfloat162float(__float2bfloat16_rn(b)));
    return *(unsigned*)&p;
}

// ---------------- merged init: te + syndrome nodes + adjacency ------------------
__global__ void k_init0(const int* __restrict__ t, const float* __restrict__ time_table,
                        const float* __restrict__ r_t, const int* __restrict__ pcm) {
    int blk = blockIdx.x;
    int lane = threadIdx.x & 31;
    if (blk < 512) {
        int w = blk * 8 + (threadIdx.x >> 5);
        int b = w >> 9, m = w & 511;
        int cnt = 0;
        #pragma unroll
        for (int i = 0; i < 32; i++) {
            int col = lane + i * 32;
            bool pred = (pcm[(size_t)m * Nc + col] != 0) && (r_t[(size_t)b * Nc + col] < 0.0f);
            cnt += __popc(__ballot_sync(0xffffffffu, pred));
        }
        if (lane == 0) g_nodes[(size_t)b * Sc + Nc + m] = (float)(cnt & 1);
    } else if (blk < 704) {
        int s = (blk - 512) * 8 + (threadIdx.x >> 5);
        unsigned lt = (1u << lane) - 1u;
        int* adj = g_adj + s * MAXNB;
        int cnt = 1;
        if (lane == 0) adj[0] = s;
        if (s < Nc) {
            #pragma unroll
            for (int i = 0; i < 16; i++) {
                int m = lane + i * 32;
                bool pred = pcm[(size_t)m * Nc + s] != 0;
                unsigned bal = __ballot_sync(0xffffffffu, pred);
                int rank = __popc(bal & lt);
                if (pred && cnt + rank < MAXNB) adj[cnt + rank] = Nc + m;
                cnt += __popc(bal);
            }
        } else {
            const int* row = pcm + (size_t)(s - Nc) * Nc;
            #pragma unroll
            for (int i = 0; i < 32; i++) {
                int n = lane + i * 32;
                bool pred = row[n] != 0;
                unsigned bal = __ballot_sync(0xffffffffu, pred);
                int rank = __popc(bal & lt);
                if (pred && cnt + rank < MAXNB) adj[cnt + rank] = n;
                cnt += __popc(bal);
            }
        }
        if (lane == 0) g_adjcnt[s] = cnt < MAXNB ? cnt : MAXNB;
    } else {
        #pragma unroll
        for (int i = threadIdx.x; i < Bc * Dc; i += 256) {
            int b = i >> 7, d = i & 127;
            g_te[i] = time_table[t[b] * Dc + d];
        }
    }
}

__global__ void k_xinit(const float* __restrict__ src_embed, const float* __restrict__ r_t) {
    int i = blockIdx.x * blockDim.x + threadIdx.x;
    if (i >= ROWS * Dc) return;
    int d = i & 127;
    int bs = i >> 7;
    int b = bs / Sc, s = bs % Sc;
    float node = (s < Nc) ? fabsf(r_t[(size_t)b * Nc + s]) : g_nodes[bs];
    g_x[i] = src_embed[s * Dc + d] * node * g_te[b * Dc + d];
}

// ---------------- weight transpose+split ----------------------------------------
__global__ void k_wsplit(const float* __restrict__ Wq, const float* __restrict__ Wk,
                         const float* __restrict__ Wv, const float* __restrict__ Wo,
                         const float* __restrict__ W1, const float* __restrict__ W2) {
    __shared__ float s[32][33];
    int bid = blockIdx.x;
    int l = bid / 192, tt = bid % 192;
    const float* src; int Nn, k0, n0; size_t dstBase; int dstLd;
    if (tt < 64) {
        int seg = tt >> 4, local = tt & 15;
        k0 = (local >> 2) * 32; n0 = (local & 3) * 32; Nn = 128; dstLd = 128;
        if      (seg == 0) { src = Wq + (size_t)l * 16384; dstBase = (size_t)l * PER_L; }
        else if (seg == 1) { src = Wk + (size_t)l * 16384; dstBase = (size_t)l * PER_L + 16384; }
        else if (seg == 2) { src = Wv + (size_t)l * 16384; dstBase = (size_t)l * PER_L + 32768; }
        else               { src = Wo + (size_t)l * 16384; dstBase = (size_t)l * PER_L + 49152; }
    } else if (tt < 128) {
        int local = tt - 64;
        k0 = (local >> 4) * 32; n0 = (local & 15) * 32; Nn = 512; dstLd = 128;
        src = W1 + (size_t)l * 65536; dstBase = (size_t)l * PER_L + 65536;
    } else {
        int local = tt - 128;
        k0 = (local >> 2) * 32; n0 = (local & 3) * 32; Nn = 128; dstLd = 512;
        src = W2 + (size_t)l * 65536; dstBase = (size_t)l * PER_L + 131072;
    }
    int tx = threadIdx.x & 31, ty = threadIdx.x >> 5;
    #pragma unroll
    for (int j = 0; j < 4; j++)
        s[ty + j * 8][tx] = src[(size_t)(k0 + ty + j * 8) * Nn + n0 + tx];
    __syncthreads();
    #pragma unroll
    for (int j = 0; j < 4; j++) {
        int n = n0 + ty + j * 8;
        float v = s[tx][ty + j * 8];
        __nv_bfloat16 hi, lo;
        split_bf16(v, hi, lo);
        size_t o = dstBase + (size_t)n * dstLd + k0 + tx;
        g_wThi[o] = hi;
        g_wTlo[o] = lo;
    }
}

// ---------------- fused LN + bf16x3 GEMM, ldmatrix inner loop --------------------
#define SW 68
#define A_WORDS (128 * SW)
#define B_WORDS (64 * SW)
#define SMEMB ((2 * A_WORDS + 2 * B_WORDS) * 4)
#define ROWS16B (16 * SW * 4)

__device__ __forceinline__ void mma_bf16(float* c, const unsigned* a, const unsigned* b) {
    asm volatile(
        "mma.sync.aligned.m16n8k16.row.col.f32.bf16.bf16.f32 "
        "{%0,%1,%2,%3}, {%4,%5,%6,%7}, {%8,%9}, {%0,%1,%2,%3};"
        : "+f"(c[0]), "+f"(c[1]), "+f"(c[2]), "+f"(c[3])
        : "r"(a[0]), "r"(a[1]), "r"(a[2]), "r"(a[3]), "r"(b[0]), "r"(b[1]));
}
__device__ __forceinline__ void ldsm4(unsigned* d, unsigned addr) {
    asm volatile("ldmatrix.sync.aligned.m8n8.x4.shared.b16 {%0,%1,%2,%3}, [%4];"
                 : "=r"(d[0]), "=r"(d[1]), "=r"(d[2]), "=r"(d[3]) : "r"(addr));
}

template <int AMODE, int EPI, int NT>   // BN = 16*NT
__global__ void __launch_bounds__(256, 2)
k_gemm(const float* __restrict__ Xf,
       const __nv_bfloat16* __restrict__ Ahi, const __nv_bfloat16* __restrict__ Alo,
       const float* __restrict__ gg, const float* __restrict__ bb,
       const __nv_bfloat16* __restrict__ Bhi, const __nv_bfloat16* __restrict__ Blo,
       float* __restrict__ C, __nv_bfloat16* __restrict__ Chi, __nv_bfloat16* __restrict__ Clo,
       int K, int Nn) {
    extern __shared__ unsigned smw[];
    unsigned* sAhi = smw;
    unsigned* sAlo = sAhi + A_WORDS;
    unsigned* sBhi = sAlo + A_WORDS;
    unsigned* sBlo = sBhi + B_WORDS;

    const int tid = threadIdx.x;
    const int lane = tid & 31, warp = tid >> 5;
    const int wm = (warp >> 1) * 32, wn = (warp & 1) * (NT * 8);
    const int g = lane >> 2, q4 = lane & 3;
    const int BN = 16 * NT;
    const int rowBase = blockIdx.y * 128, colBase = blockIdx.x * BN;

    const unsigned aOff = (unsigned)((wm + (lane & 15)) * SW + (lane >> 4) * 4) * 4u;
    const unsigned bOff = (unsigned)((wn + ((lane >> 4) & 1) * 8 + (lane & 7)) * SW
                                     + ((lane >> 3) & 1) * 4) * 4u;
    const unsigned aHiBase = (unsigned)__cvta_generic_to_shared(sAhi) + aOff;
    const unsigned aLoBase = (unsigned)__cvta_generic_to_shared(sAlo) + aOff;
    const unsigned bHiBase = (unsigned)__cvta_generic_to_shared(sBhi) + bOff;
    const unsigned bLoBase = (unsigned)__cvta_generic_to_shared(sBlo) + bOff;

    float acc[2][NT][4];
    #pragma unroll
    for (int mt = 0; mt < 2; mt++)
        #pragma unroll
        for (int nt = 0; nt < NT; nt++)
            #pragma unroll
            for (int i = 0; i < 4; i++) acc[mt][nt][i] = 0.0f;

    float4 gv, bv, tv;
    if (AMODE != 0) {
        gv = *(const float4*)&gg[lane * 4];
        bv = *(const float4*)&bb[lane * 4];
        if (AMODE == 2) {
            int bIdx = rowBase / Sc;
            tv = *(const float4*)&g_te[bIdx * Dc + lane * 4];
        }
    }

    for (int kt = 0; kt < K; kt += 128) {
        if (kt) __syncthreads();
        // ---- A slice ----
        if (AMODE == 0) {
            #pragma unroll
            for (int i = 0; i < 8; i++) {
                int t = tid + i * 256;
                int r = t >> 4, c = t & 15;
                size_t goff = (size_t)(rowBase + r) * K + kt + c * 8;
                *(uint4*)&sAhi[r * SW + c * 4] = *(const uint4*)(Ahi + goff);
                *(uint4*)&sAlo[r * SW + c * 4] = *(const uint4*)(Alo + goff);
            }
        } else {
            #pragma unroll
            for (int p = 0; p < 16; p++) {
                int r = warp * 16 + p;
                float4 xv = *(const float4*)&Xf[(size_t)(rowBase + r) * 128 + lane * 4];
                float s1 = xv.x + xv.y + xv.z + xv.w;
                float s2 = xv.x * xv.x + xv.y * xv.y + xv.z * xv.z + xv.w * xv.w;
                #pragma unroll
                for (int o = 16; o > 0; o >>= 1) {
                    s1 += __shfl_xor_sync(0xffffffffu, s1, o);
                    s2 += __shfl_xor_sync(0xffffffffu, s2, o);
                }
                float mean = s1 * (1.0f / 128.0f);
                float var  = s2 * (1.0f / 128.0f) - mean * mean;
                float inv  = rsqrtf(var + 1e-5f);
                float o0 = (xv.x - mean) * inv * gv.x + bv.x;
                float o1 = (xv.y - mean) * inv * gv.y + bv.y;
                float o2 = (xv.z - mean) * inv * gv.z + bv.z;
                float o3 = (xv.w - mean) * inv * gv.w + bv.w;
                if (AMODE == 2) { o0 *= tv.x; o1 *= tv.y; o2 *= tv.z; o3 *= tv.w; }
                sAhi[r * SW + lane * 2]     = pack2hi(o0, o1);
                sAhi[r * SW + lane * 2 + 1] = pack2hi(o2, o3);
                sAlo[r * SW + lane * 2]     = pack2lo(o0, o1);
                sAlo[r * SW + lane * 2 + 1] = pack2lo(o2, o3);
            }
        }
        // ---- B slice ----
        #pragma unroll
        for (int i = 0; i < NT; i++) {
            int t = tid + i * 256;
            int n = t >> 4, c = t & 15;
            size_t goff = (size_t)(colBase + n) * K + kt + c * 8;
            *(uint4*)&sBhi[n * SW + c * 4] = *(const uint4*)(Bhi + goff);
            *(uint4*)&sBlo[n * SW + c * 4] = *(const uint4*)(Blo + goff);
        }
        __syncthreads();

        #pragma unroll
        for (int ks = 0; ks < 8; ks++) {
            const unsigned ko = ks * 32u;
            unsigned ah[2][4], al[2][4], bh[NT][2], bl[NT][2];
            #pragma unroll
            for (int mt = 0; mt < 2; mt++) {
                ldsm4(ah[mt], aHiBase + mt * ROWS16B + ko);
                ldsm4(al[mt], aLoBase + mt * ROWS16B + ko);
            }
            #pragma unroll
            for (int pr = 0; pr < NT / 2; pr++) {
                unsigned t0[4], t1[4];
                ldsm4(t0, bHiBase + pr * ROWS16B + ko);
                ldsm4(t1, bLoBase + pr * ROWS16B + ko);
                bh[pr * 2][0] = t0[0]; bh[pr * 2][1] = t0[1];
                bh[pr * 2 + 1][0] = t0[2]; bh[pr * 2 + 1][1] = t0[3];
                bl[pr * 2][0] = t1[0]; bl[pr * 2][1] = t1[1];
                bl[pr * 2 + 1][0] = t1[2]; bl[pr * 2 + 1][1] = t1[3];
            }
            #pragma unroll
            for (int mt = 0; mt < 2; mt++)
                #pragma unroll
                for (int nt = 0; nt < NT; nt++) {
                    mma_bf16(acc[mt][nt], ah[mt], bh[nt]);
                    mma_bf16(acc[mt][nt], ah[mt], bl[nt]);
                    mma_bf16(acc[mt][nt], al[mt], bh[nt]);
                }
        }
    }

    // ---- epilogue ----
    #pragma unroll
    for (int mt = 0; mt < 2; mt++)
        #pragma unroll
        for (int nt = 0; nt < NT; nt++) {
            int r = rowBase + wm + mt * 16 + g;
            int c = colBase + wn + nt * 8 + q4 * 2;
            float* a = acc[mt][nt];
            if (EPI == 0) {
                *(float2*)&C[(size_t)r * Nn + c]       = make_float2(a[0], a[1]);
                *(float2*)&C[(size_t)(r + 8) * Nn + c] = make_float2(a[2], a[3]);
            } else if (EPI == 1) {
                float2 v0 = *(const float2*)&C[(size_t)r * Nn + c];
                float2 v1 = *(const float2*)&C[(size_t)(r + 8) * Nn + c];
                v0.x += a[0]; v0.y += a[1]; v1.x += a[2]; v1.y += a[3];
                *(float2*)&C[(size_t)r * Nn + c]       = v0;
                *(float2*)&C[(size_t)(r + 8) * Nn + c] = v1;
            } else {
                #pragma unroll
                for (int rr = 0; rr < 2; rr++) {
                    float v0 = fmaxf(a[rr * 2 + 0], 0.0f);
                    float v1 = fmaxf(a[rr * 2 + 1], 0.0f);
                    size_t o = (size_t)(r + rr * 8) * Nn + c;
                    *(unsigned*)&Chi[o] = pack2hi(v0, v1);
                    *(unsigned*)&Clo[o] = pack2lo(v0, v1);
                }
            }
        }
}

// ---------------- sparse attention: warp per row, online softmax -----------------
__global__ void __launch_bounds__(256)
k_attn(const float* __restrict__ qkv,
       __nv_bfloat16* __restrict__ ohi, __nv_bfloat16* __restrict__ olo) {
    int warp = threadIdx.x >> 5, lane = threadIdx.x & 31;
    int bs = blockIdx.x * 8 + warp;
    int b = bs / Sc, s = bs % Sc;
    int cnt = g_adjcnt[s];
    const int* adj = g_adj + s * MAXNB;

    float4 qv = *(const float4*)&qkv[(size_t)bs * 384 + lane * 4];

    float m = -1e30f, l = 0.0f;
    float4 acc = make_float4(0.0f, 0.0f, 0.0f, 0.0f);

    for (int j = 0; j < cnt; j++) {
        int n = adj[j];
        const float* kr = qkv + ((size_t)b * Sc + n) * 384 + 128;
        float4 kv = *(const float4*)&kr[lane * 4];
        float d = qv.x * kv.x + qv.y * kv.y + qv.z * kv.z + qv.w * kv.w;
        d += __shfl_xor_sync(0xffffffffu, d, 1);
        d += __shfl_xor_sync(0xffffffffu, d, 2);
        float sc = d * 0.25f;
        float mn = fmaxf(m, sc);
        float scale = __expf(m - mn);
        float p = __expf(sc - mn);
        l = l * scale + p;
        float4 vv = *(const float4*)&kr[128 + lane * 4];
        acc.x = acc.x * scale + p * vv.x;
        acc.y = acc.y * scale + p * vv.y;
        acc.z = acc.z * scale + p * vv.z;
        acc.w = acc.w * scale + p * vv.w;
        m = mn;
    }

    float inv = 1.0f / l;
    float v0 = acc.x * inv, v1 = acc.y * inv, v2 = acc.z * inv, v3 = acc.w * inv;
    size_t o = (size_t)bs * Dc + lane * 4;
    *(unsigned*)&ohi[o]     = pack2hi(v0, v1);
    *(unsigned*)&ohi[o + 2] = pack2hi(v2, v3);
    *(unsigned*)&olo[o]     = pack2lo(v0, v1);
    *(unsigned*)&olo[o + 2] = pack2lo(v2, v3);
}

// ---------------- final projection -----------------------------------------------
__global__ void k_out(const float* __restrict__ fc_w, const float* __restrict__ fc_b,
                      float* __restrict__ out) {
    int row = blockIdx.x * 8 + (threadIdx.x >> 5);
    if (row >= ROWS) return;
    int lane = threadIdx.x & 31;
    float sum = 0.0f;
    #pragma unroll
    for (int d = lane; d < Dc; d += 32) sum += g_x[(size_t)row * Dc + d] * fc_w[d];
    #pragma unroll
    for (int off = 16; off > 0; off >>= 1) sum += __shfl_xor_sync(0xffffffffu, sum, off);
    if (lane == 0) out[row] = sum + fc_b[0];
}

// ---------------- launcher ---------------------------------------------------------
extern "C" void kernel_launch(void* const* d_in, const int* in_sizes, int n_in,
                              void* d_out, int out_size) {
    const float* r_t        = (const float*)d_in[0];
    const int*   t          = (const int*)  d_in[1];
    const int*   pcm        = (const int*)  d_in[2];
    const float* src_embed  = (const float*)d_in[4];
    const float* time_table = (const float*)d_in[5];
    const float* Wq = (const float*)d_in[6];
    const float* Wk = (const float*)d_in[7];
    const float* Wv = (const float*)d_in[8];
    const float* Wo = (const float*)d_in[9];
    const float* W1 = (const float*)d_in[10];
    const float* W2 = (const float*)d_in[11];
    const float* g1 = (const float*)d_in[12];
    const float* b1 = (const float*)d_in[13];
    const float* g2 = (const float*)d_in[14];
    const float* b2 = (const float*)d_in[15];
    const float* fc_w = (const float*)d_in[16];
    const float* fc_b = (const float*)d_in[17];
    float* out = (float*)d_out;

    float *px, *pqkv;
    __nv_bfloat16 *whi, *wlo, *ohi, *olo, *fhi, *flo;
    cudaGetSymbolAddress((void**)&px,   g_x);
    cudaGetSymbolAddress((void**)&pqkv, g_qkv);
    cudaGetSymbolAddress((void**)&whi,  g_wThi);
    cudaGetSymbolAddress((void**)&wlo,  g_wTlo);
    cudaGetSymbolAddress((void**)&ohi,  g_ohi);
    cudaGetSymbolAddress((void**)&olo,  g_olo);
    cudaGetSymbolAddress((void**)&fhi,  g_fhi);
    cudaGetSymbolAddress((void**)&flo,  g_flo);

    static int smemSet = 0;
    if (!smemSet) {
        cudaFuncSetAttribute(k_gemm<1,0,4>, cudaFuncAttributeMaxDynamicSharedMemorySize, SMEMB);
        cudaFuncSetAttribute(k_gemm<0,1,2>, cudaFuncAttributeMaxDynamicSharedMemorySize, SMEMB);
        cudaFuncSetAttribute(k_gemm<2,2,4>, cudaFuncAttributeMaxDynamicSharedMemorySize, SMEMB);
        // Ask for the FULL 228KB smem carveout so two 104KB CTAs co-reside per SM.
        cudaFuncSetAttribute(k_gemm<1,0,4>, cudaFuncAttributePreferredSharedMemoryCarveout, 100);
        cudaFuncSetAttribute(k_gemm<0,1,2>, cudaFuncAttributePreferredSharedMemoryCarveout, 100);
        cudaFuncSetAttribute(k_gemm<2,2,4>, cudaFuncAttributePreferredSharedMemoryCarveout, 100);
        smemSet = 1;
    }

    k_init0<<<705, 256>>>(t, time_table, r_t, pcm);
    k_xinit<<<(ROWS * Dc + 255) / 256, 256>>>(src_embed, r_t);
    k_wsplit<<<Lc * 192, 256>>>(Wq, Wk, Wv, Wo, W1, W2);

    dim3 gQKV(6, 96);    // BN=64
    dim3 gD32(4, 96);    // BN=32 (384 CTAs)
    dim3 gF  (8, 96);    // BN=64

    for (int l = 0; l < Lc; l++) {
        const __nv_bfloat16* lwh = whi + (size_t)l * PER_L;
        const __nv_bfloat16* lwl = wlo + (size_t)l * PER_L;

        k_gemm<1,0,4><<<gQKV, 256, SMEMB>>>(px, nullptr, nullptr, g1 + l * Dc, b1 + l * Dc,
                                            lwh, lwl, pqkv, nullptr, nullptr, 128, 384);
        k_attn<<<ROWS / 8, 256>>>(pqkv, ohi, olo);
        k_gemm<0,1,2><<<gD32, 256, SMEMB>>>(nullptr, ohi, olo, nullptr, nullptr,
                                            lwh + 49152, lwl + 49152, px, nullptr, nullptr, 128, 128);
        k_gemm<2,2,4><<<gF, 256, SMEMB>>>(px, nullptr, nullptr, g2 + l * Dc, b2 + l * Dc,
                                          lwh + 65536, lwl + 65536, nullptr, fhi, flo, 128, 512);
        k_gemm<0,1,2><<<gD32, 256, SMEMB>>>(nullptr, fhi, flo, nullptr, nullptr,
                                            lwh + 131072, lwl + 131072, px, nullptr, nullptr, 512, 128);
    }

    k_out<<<(ROWS + 7) / 8, 256>>>(fc_w, fc_b, out);
}

// round 14
// speedup vs baseline: 1.2322x; 1.0115x over previous
#include <cuda_runtime.h>
#include <cuda_bf16.h>
#include <math.h>

#define Bc      8
#define Nc      1024
#define Mc      512
#define Dc      128
#define Lc      6
#define DFFc    512
#define Sc      1536
#define HDc     16
#define MAXNB   64
#define ROWS    12288
#define PER_L   196608

// ---------------- scratch ------------------------------------------------------
__device__ float g_x  [ROWS * Dc];
__device__ float g_qkv[ROWS * 384];
__device__ float g_te [Bc * Dc];
__device__ float g_nodes[ROWS];
__device__ int   g_adj[Sc * MAXNB];
__device__ int   g_adjcnt[Sc];

__device__ __nv_bfloat16 g_wThi[Lc * PER_L];
__device__ __nv_bfloat16 g_wTlo[Lc * PER_L];
__device__ __nv_bfloat16 g_ohi[ROWS * Dc];
__device__ __nv_bfloat16 g_olo[ROWS * Dc];
__device__ __nv_bfloat16 g_fhi[ROWS * DFFc];
__device__ __nv_bfloat16 g_flo[ROWS * DFFc];

__device__ __forceinline__ void split_bf16(float v, __nv_bfloat16& hi, __nv_bfloat16& lo) {
    hi = __float2bfloat16_rn(v);
    lo = __float2bfloat16_rn(v - __bfloat162float(hi));
}
__device__ __forceinline__ unsigned pack2hi(float a, float b) {
    __nv_bfloat162 p; p.x = __float2bfloat16_rn(a); p.y = __float2bfloat16_rn(b);
    return *(unsigned*)&p;
}
__device__ __forceinline__ unsigned pack2lo(float a, float b) {
    __nv_bfloat162 p;
    p.x = __float2bfloat16_rn(a - __bfloat162float(__float2bfloat16_rn(a)));
    p.y = __float2bfloat16_rn(b - __bfloat162float(__float2bfloat16_rn(b)));
    return *(unsigned*)&p;
}

// ---------------- cp.async helpers ----------------------------------------------
__device__ __forceinline__ void cp16(unsigned dst, const void* src) {
    asm volatile("cp.async.cg.shared.global [%0], [%1], 16;" :: "r"(dst), "l"(src));
}
__device__ __forceinline__ void cp_commit() { asm volatile("cp.async.commit_group;"); }
__device__ __forceinline__ void cp_wait0()  { asm volatile("cp.async.wait_group 0;" ::: "memory"); }

// ---------------- merged init: te + syndrome nodes + adjacency ------------------
__global__ void k_init0(const int* __restrict__ t, const float* __restrict__ time_table,
                        const float* __restrict__ r_t, const int* __restrict__ pcm) {
    int blk = blockIdx.x;
    int lane = threadIdx.x & 31;
    if (blk < 512) {
        int w = blk * 8 + (threadIdx.x >> 5);
        int b = w >> 9, m = w & 511;
        int cnt = 0;
        #pragma unroll
        for (int i = 0; i < 32; i++) {
            int col = lane + i * 32;
            bool pred = (pcm[(size_t)m * Nc + col] != 0) && (r_t[(size_t)b * Nc + col] < 0.0f);
            cnt += __popc(__ballot_sync(0xffffffffu, pred));
        }
        if (lane == 0) g_nodes[(size_t)b * Sc + Nc + m] = (float)(cnt & 1);
    } else if (blk < 704) {
        int s = (blk - 512) * 8 + (threadIdx.x >> 5);
        unsigned lt = (1u << lane) - 1u;
        int* adj = g_adj + s * MAXNB;
        int cnt = 1;
        if (lane == 0) adj[0] = s;
        if (s < Nc) {
            #pragma unroll
            for (int i = 0; i < 16; i++) {
                int m = lane + i * 32;
                bool pred = pcm[(size_t)m * Nc + s] != 0;
                unsigned bal = __ballot_sync(0xffffffffu, pred);
                int rank = __popc(bal & lt);
                if (pred && cnt + rank < MAXNB) adj[cnt + rank] = Nc + m;
                cnt += __popc(bal);
            }
        } else {
            const int* row = pcm + (size_t)(s - Nc) * Nc;
            #pragma unroll
            for (int i = 0; i < 32; i++) {
                int n = lane + i * 32;
                bool pred = row[n] != 0;
                unsigned bal = __ballot_sync(0xffffffffu, pred);
                int rank = __popc(bal & lt);
                if (pred && cnt + rank < MAXNB) adj[cnt + rank] = n;
                cnt += __popc(bal);
            }
        }
        if (lane == 0) g_adjcnt[s] = cnt < MAXNB ? cnt : MAXNB;
    } else {
        #pragma unroll
        for (int i = threadIdx.x; i < Bc * Dc; i += 256) {
            int b = i >> 7, d = i & 127;
            g_te[i] = time_table[t[b] * Dc + d];
        }
    }
}

__global__ void k_xinit(const float* __restrict__ src_embed, const float* __restrict__ r_t) {
    int i = blockIdx.x * blockDim.x + threadIdx.x;
    if (i >= ROWS * Dc) return;
    int d = i & 127;
    int bs = i >> 7;
    int b = bs / Sc, s = bs % Sc;
    float node = (s < Nc) ? fabsf(r_t[(size_t)b * Nc + s]) : g_nodes[bs];
    g_x[i] = src_embed[s * Dc + d] * node * g_te[b * Dc + d];
}

// ---------------- weight transpose+split ----------------------------------------
__global__ void k_wsplit(const float* __restrict__ Wq, const float* __restrict__ Wk,
                         const float* __restrict__ Wv, const float* __restrict__ Wo,
                         const float* __restrict__ W1, const float* __restrict__ W2) {
    __shared__ float s[32][33];
    int bid = blockIdx.x;
    int l = bid / 192, tt = bid % 192;
    const float* src; int Nn, k0, n0; size_t dstBase; int dstLd;
    if (tt < 64) {
        int seg = tt >> 4, local = tt & 15;
        k0 = (local >> 2) * 32; n0 = (local & 3) * 32; Nn = 128; dstLd = 128;
        if      (seg == 0) { src = Wq + (size_t)l * 16384; dstBase = (size_t)l * PER_L; }
        else if (seg == 1) { src = Wk + (size_t)l * 16384; dstBase = (size_t)l * PER_L + 16384; }
        else if (seg == 2) { src = Wv + (size_t)l * 16384; dstBase = (size_t)l * PER_L + 32768; }
        else               { src = Wo + (size_t)l * 16384; dstBase = (size_t)l * PER_L + 49152; }
    } else if (tt < 128) {
        int local = tt - 64;
        k0 = (local >> 4) * 32; n0 = (local & 15) * 32; Nn = 512; dstLd = 128;
        src = W1 + (size_t)l * 65536; dstBase = (size_t)l * PER_L + 65536;
    } else {
        int local = tt - 128;
        k0 = (local >> 2) * 32; n0 = (local & 3) * 32; Nn = 128; dstLd = 512;
        src = W2 + (size_t)l * 65536; dstBase = (size_t)l * PER_L + 131072;
    }
    int tx = threadIdx.x & 31, ty = threadIdx.x >> 5;
    #pragma unroll
    for (int j = 0; j < 4; j++)
        s[ty + j * 8][tx] = src[(size_t)(k0 + ty + j * 8) * Nn + n0 + tx];
    __syncthreads();
    #pragma unroll
    for (int j = 0; j < 4; j++) {
        int n = n0 + ty + j * 8;
        float v = s[tx][ty + j * 8];
        __nv_bfloat16 hi, lo;
        split_bf16(v, hi, lo);
        size_t o = dstBase + (size_t)n * dstLd + k0 + tx;
        g_wThi[o] = hi;
        g_wTlo[o] = lo;
    }
}

// ---------------- fused LN + bf16x3 GEMM, ldmatrix + cp.async --------------------
#define SW 68
#define A_WORDS (128 * SW)
#define B_WORDS (64 * SW)
#define SMEMB ((2 * A_WORDS + 2 * B_WORDS) * 4)
#define ROWS16B (16 * SW * 4)

__device__ __forceinline__ void mma_bf16(float* c, const unsigned* a, const unsigned* b) {
    asm volatile(
        "mma.sync.aligned.m16n8k16.row.col.f32.bf16.bf16.f32 "
        "{%0,%1,%2,%3}, {%4,%5,%6,%7}, {%8,%9}, {%0,%1,%2,%3};"
        : "+f"(c[0]), "+f"(c[1]), "+f"(c[2]), "+f"(c[3])
        : "r"(a[0]), "r"(a[1]), "r"(a[2]), "r"(a[3]), "r"(b[0]), "r"(b[1]));
}
__device__ __forceinline__ void ldsm4(unsigned* d, unsigned addr) {
    asm volatile("ldmatrix.sync.aligned.m8n8.x4.shared.b16 {%0,%1,%2,%3}, [%4];"
                 : "=r"(d[0]), "=r"(d[1]), "=r"(d[2]), "=r"(d[3]) : "r"(addr));
}

template <int AMODE, int EPI, int NT>   // BN = 16*NT
__global__ void __launch_bounds__(256, 2)
k_gemm(const float* __restrict__ Xf,
       const __nv_bfloat16* __restrict__ Ahi, const __nv_bfloat16* __restrict__ Alo,
       const float* __restrict__ gg, const float* __restrict__ bb,
       const __nv_bfloat16* __restrict__ Bhi, const __nv_bfloat16* __restrict__ Blo,
       float* __restrict__ C, __nv_bfloat16* __restrict__ Chi, __nv_bfloat16* __restrict__ Clo,
       int K, int Nn) {
    extern __shared__ unsigned smw[];
    unsigned* sAhi = smw;
    unsigned* sAlo = sAhi + A_WORDS;
    unsigned* sBhi = sAlo + A_WORDS;
    unsigned* sBlo = sBhi + B_WORDS;

    const int tid = threadIdx.x;
    const int lane = tid & 31, warp = tid >> 5;
    const int wm = (warp >> 1) * 32, wn = (warp & 1) * (NT * 8);
    const int g = lane >> 2, q4 = lane & 3;
    const int BN = 16 * NT;
    const int rowBase = blockIdx.y * 128, colBase = blockIdx.x * BN;

    const unsigned sAhiAddr = (unsigned)__cvta_generic_to_shared(sAhi);
    const unsigned sAloAddr = (unsigned)__cvta_generic_to_shared(sAlo);
    const unsigned sBhiAddr = (unsigned)__cvta_generic_to_shared(sBhi);
    const unsigned sBloAddr = (unsigned)__cvta_generic_to_shared(sBlo);

    const unsigned aOff = (unsigned)((wm + (lane & 15)) * SW + (lane >> 4) * 4) * 4u;
    const unsigned bOff = (unsigned)((wn + ((lane >> 4) & 1) * 8 + (lane & 7)) * SW
                                     + ((lane >> 3) & 1) * 4) * 4u;
    const unsigned aHiBase = sAhiAddr + aOff;
    const unsigned aLoBase = sAloAddr + aOff;
    const unsigned bHiBase = sBhiAddr + bOff;
    const unsigned bLoBase = sBloAddr + bOff;

    float acc[2][NT][4];
    #pragma unroll
    for (int mt = 0; mt < 2; mt++)
        #pragma unroll
        for (int nt = 0; nt < NT; nt++)
            #pragma unroll
            for (int i = 0; i < 4; i++) acc[mt][nt][i] = 0.0f;

    float4 gv, bv, tv;
    if (AMODE != 0) {
        gv = *(const float4*)&gg[lane * 4];
        bv = *(const float4*)&bb[lane * 4];
        if (AMODE == 2) {
            int bIdx = rowBase / Sc;
            tv = *(const float4*)&g_te[bIdx * Dc + lane * 4];
        }
    }

    for (int kt = 0; kt < K; kt += 128) {
        if (kt) __syncthreads();

        // ---- B slice via cp.async, issued FIRST (overlaps with LN below) ----
        #pragma unroll
        for (int i = 0; i < NT; i++) {
            int t = tid + i * 256;
            int n = t >> 4, c = t & 15;
            size_t goff = (size_t)(colBase + n) * K + kt + c * 8;
            unsigned sm = (unsigned)(n * SW + c * 4) * 4u;
            cp16(sBhiAddr + sm, Bhi + goff);
            cp16(sBloAddr + sm, Blo + goff);
        }

        if (AMODE == 0) {
            // ---- A slice via cp.async ----
            #pragma unroll
            for (int i = 0; i < 8; i++) {
                int t = tid + i * 256;
                int r = t >> 4, c = t & 15;
                size_t goff = (size_t)(rowBase + r) * K + kt + c * 8;
                unsigned sm = (unsigned)(r * SW + c * 4) * 4u;
                cp16(sAhiAddr + sm, Ahi + goff);
                cp16(sAloAddr + sm, Alo + goff);
            }
            cp_commit();
            cp_wait0();
        } else {
            cp_commit();
            // ---- fused LayerNorm runs while B copies are in flight ----
            #pragma unroll
            for (int p = 0; p < 16; p++) {
                int r = warp * 16 + p;
                float4 xv = *(const float4*)&Xf[(size_t)(rowBase + r) * 128 + lane * 4];
                float s1 = xv.x + xv.y + xv.z + xv.w;
                float s2 = xv.x * xv.x + xv.y * xv.y + xv.z * xv.z + xv.w * xv.w;
                #pragma unroll
                for (int o = 16; o > 0; o >>= 1) {
                    s1 += __shfl_xor_sync(0xffffffffu, s1, o);
                    s2 += __shfl_xor_sync(0xffffffffu, s2, o);
                }
                float mean = s1 * (1.0f / 128.0f);
                float var  = s2 * (1.0f / 128.0f) - mean * mean;
                float inv  = rsqrtf(var + 1e-5f);
                float o0 = (xv.x - mean) * inv * gv.x + bv.x;
                float o1 = (xv.y - mean) * inv * gv.y + bv.y;
                float o2 = (xv.z - mean) * inv * gv.z + bv.z;
                float o3 = (xv.w - mean) * inv * gv.w + bv.w;
                if (AMODE == 2) { o0 *= tv.x; o1 *= tv.y; o2 *= tv.z; o3 *= tv.w; }
                sAhi[r * SW + lane * 2]     = pack2hi(o0, o1);
                sAhi[r * SW + lane * 2 + 1] = pack2hi(o2, o3);
                sAlo[r * SW + lane * 2]     = pack2lo(o0, o1);
                sAlo[r * SW + lane * 2 + 1] = pack2lo(o2, o3);
            }
            cp_wait0();
        }
        __syncthreads();

        #pragma unroll
        for (int ks = 0; ks < 8; ks++) {
            const unsigned ko = ks * 32u;
            unsigned ah[2][4], al[2][4], bh[NT][2], bl[NT][2];
            #pragma unroll
            for (int mt = 0; mt < 2; mt++) {
                ldsm4(ah[mt], aHiBase + mt * ROWS16B + ko);
                ldsm4(al[mt], aLoBase + mt * ROWS16B + ko);
            }
            #pragma unroll
            for (int pr = 0; pr < NT / 2; pr++) {
                unsigned t0[4], t1[4];
                ldsm4(t0, bHiBase + pr * ROWS16B + ko);
                ldsm4(t1, bLoBase + pr * ROWS16B + ko);
                bh[pr * 2][0] = t0[0]; bh[pr * 2][1] = t0[1];
                bh[pr * 2 + 1][0] = t0[2]; bh[pr * 2 + 1][1] = t0[3];
                bl[pr * 2][0] = t1[0]; bl[pr * 2][1] = t1[1];
                bl[pr * 2 + 1][0] = t1[2]; bl[pr * 2 + 1][1] = t1[3];
            }
            #pragma unroll
            for (int mt = 0; mt < 2; mt++)
                #pragma unroll
                for (int nt = 0; nt < NT; nt++) {
                    mma_bf16(acc[mt][nt], ah[mt], bh[nt]);
                    mma_bf16(acc[mt][nt], ah[mt], bl[nt]);
                    mma_bf16(acc[mt][nt], al[mt], bh[nt]);
                }
        }
    }

    // ---- epilogue ----
    #pragma unroll
    for (int mt = 0; mt < 2; mt++)
        #pragma unroll
        for (int nt = 0; nt < NT; nt++) {
            int r = rowBase + wm + mt * 16 + g;
            int c = colBase + wn + nt * 8 + q4 * 2;
            float* a = acc[mt][nt];
            if (EPI == 0) {
                *(float2*)&C[(size_t)r * Nn + c]       = make_float2(a[0], a[1]);
                *(float2*)&C[(size_t)(r + 8) * Nn + c] = make_float2(a[2], a[3]);
            } else if (EPI == 1) {
                float2 v0 = *(const float2*)&C[(size_t)r * Nn + c];
                float2 v1 = *(const float2*)&C[(size_t)(r + 8) * Nn + c];
                v0.x += a[0]; v0.y += a[1]; v1.x += a[2]; v1.y += a[3];
                *(float2*)&C[(size_t)r * Nn + c]       = v0;
                *(float2*)&C[(size_t)(r + 8) * Nn + c] = v1;
            } else {
                #pragma unroll
                for (int rr = 0; rr < 2; rr++) {
                    float v0 = fmaxf(a[rr * 2 + 0], 0.0f);
                    float v1 = fmaxf(a[rr * 2 + 1], 0.0f);
                    size_t o = (size_t)(r + rr * 8) * Nn + c;
                    *(unsigned*)&Chi[o] = pack2hi(v0, v1);
                    *(unsigned*)&Clo[o] = pack2lo(v0, v1);
                }
            }
        }
}

// ---------------- sparse attention: warp per row, online softmax -----------------
__global__ void __launch_bounds__(256)
k_attn(const float* __restrict__ qkv,
       __nv_bfloat16* __restrict__ ohi, __nv_bfloat16* __restrict__ olo) {
    int warp = threadIdx.x >> 5, lane = threadIdx.x & 31;
    int bs = blockIdx.x * 8 + warp;
    int b = bs / Sc, s = bs % Sc;
    int cnt = g_adjcnt[s];
    const int* adj = g_adj + s * MAXNB;

    float4 qv = *(const float4*)&qkv[(size_t)bs * 384 + lane * 4];

    float m = -1e30f, l = 0.0f;
    float4 acc = make_float4(0.0f, 0.0f, 0.0f, 0.0f);

    for (int j = 0; j < cnt; j++) {
        int n = adj[j];
        const float* kr = qkv + ((size_t)b * Sc + n) * 384 + 128;
        float4 kv = *(const float4*)&kr[lane * 4];
        float d = qv.x * kv.x + qv.y * kv.y + qv.z * kv.z + qv.w * kv.w;
        d += __shfl_xor_sync(0xffffffffu, d, 1);
        d += __shfl_xor_sync(0xffffffffu, d, 2);
        float sc = d * 0.25f;
        float mn = fmaxf(m, sc);
        float scale = __expf(m - mn);
        float p = __expf(sc - mn);
        l = l * scale + p;
        float4 vv = *(const float4*)&kr[128 + lane * 4];
        acc.x = acc.x * scale + p * vv.x;
        acc.y = acc.y * scale + p * vv.y;
        acc.z = acc.z * scale + p * vv.z;
        acc.w = acc.w * scale + p * vv.w;
        m = mn;
    }

    float inv = 1.0f / l;
    float v0 = acc.x * inv, v1 = acc.y * inv, v2 = acc.z * inv, v3 = acc.w * inv;
    size_t o = (size_t)bs * Dc + lane * 4;
    *(unsigned*)&ohi[o]     = pack2hi(v0, v1);
    *(unsigned*)&ohi[o + 2] = pack2hi(v2, v3);
    *(unsigned*)&olo[o]     = pack2lo(v0, v1);
    *(unsigned*)&olo[o + 2] = pack2lo(v2, v3);
}

// ---------------- final projection -----------------------------------------------
__global__ void k_out(const float* __restrict__ fc_w, const float* __restrict__ fc_b,
                      float* __restrict__ out) {
    int row = blockIdx.x * 8 + (threadIdx.x >> 5);
    if (row >= ROWS) return;
    int lane = threadIdx.x & 31;
    float sum = 0.0f;
    #pragma unroll
    for (int d = lane; d < Dc; d += 32) sum += g_x[(size_t)row * Dc + d] * fc_w[d];
    #pragma unroll
    for (int off = 16; off > 0; off >>= 1) sum += __shfl_xor_sync(0xffffffffu, sum, off);
    if (lane == 0) out[row] = sum + fc_b[0];
}

// ---------------- launcher ---------------------------------------------------------
extern "C" void kernel_launch(void* const* d_in, const int* in_sizes, int n_in,
                              void* d_out, int out_size) {
    const float* r_t        = (const float*)d_in[0];
    const int*   t          = (const int*)  d_in[1];
    const int*   pcm        = (const int*)  d_in[2];
    const float* src_embed  = (const float*)d_in[4];
    const float* time_table = (const float*)d_in[5];
    const float* Wq = (const float*)d_in[6];
    const float* Wk = (const float*)d_in[7];
    const float* Wv = (const float*)d_in[8];
    const float* Wo = (const float*)d_in[9];
    const float* W1 = (const float*)d_in[10];
    const float* W2 = (const float*)d_in[11];
    const float* g1 = (const float*)d_in[12];
    const float* b1 = (const float*)d_in[13];
    const float* g2 = (const float*)d_in[14];
    const float* b2 = (const float*)d_in[15];
    const float* fc_w = (const float*)d_in[16];
    const float* fc_b = (const float*)d_in[17];
    float* out = (float*)d_out;

    float *px, *pqkv;
    __nv_bfloat16 *whi, *wlo, *ohi, *olo, *fhi, *flo;
    cudaGetSymbolAddress((void**)&px,   g_x);
    cudaGetSymbolAddress((void**)&pqkv, g_qkv);
    cudaGetSymbolAddress((void**)&whi,  g_wThi);
    cudaGetSymbolAddress((void**)&wlo,  g_wTlo);
    cudaGetSymbolAddress((void**)&ohi,  g_ohi);
    cudaGetSymbolAddress((void**)&olo,  g_olo);
    cudaGetSymbolAddress((void**)&fhi,  g_fhi);
    cudaGetSymbolAddress((void**)&flo,  g_flo);

    static int smemSet = 0;
    if (!smemSet) {
        cudaFuncSetAttribute(k_gemm<1,0,4>, cudaFuncAttributeMaxDynamicSharedMemorySize, SMEMB);
        cudaFuncSetAttribute(k_gemm<0,1,2>, cudaFuncAttributeMaxDynamicSharedMemorySize, SMEMB);
        cudaFuncSetAttribute(k_gemm<2,2,4>, cudaFuncAttributeMaxDynamicSharedMemorySize, SMEMB);
        cudaFuncSetAttribute(k_gemm<1,0,4>, cudaFuncAttributePreferredSharedMemoryCarveout, 100);
        cudaFuncSetAttribute(k_gemm<0,1,2>, cudaFuncAttributePreferredSharedMemoryCarveout, 100);
        cudaFuncSetAttribute(k_gemm<2,2,4>, cudaFuncAttributePreferredSharedMemoryCarveout, 100);
        smemSet = 1;
    }

    k_init0<<<705, 256>>>(t, time_table, r_t, pcm);
    k_xinit<<<(ROWS * Dc + 255) / 256, 256>>>(src_embed, r_t);
    k_wsplit<<<Lc * 192, 256>>>(Wq, Wk, Wv, Wo, W1, W2);

    dim3 gQKV(6, 96);    // BN=64
    dim3 gD32(4, 96);    // BN=32 (384 CTAs)
    dim3 gF  (8, 96);    // BN=64

    for (int l = 0; l < Lc; l++) {
        const __nv_bfloat16* lwh = whi + (size_t)l * PER_L;
        const __nv_bfloat16* lwl = wlo + (size_t)l * PER_L;

        k_gemm<1,0,4><<<gQKV, 256, SMEMB>>>(px, nullptr, nullptr, g1 + l * Dc, b1 + l * Dc,
                                            lwh, lwl, pqkv, nullptr, nullptr, 128, 384);
        k_attn<<<ROWS / 8, 256>>>(pqkv, ohi, olo);
        k_gemm<0,1,2><<<gD32, 256, SMEMB>>>(nullptr, ohi, olo, nullptr, nullptr,
                                            lwh + 49152, lwl + 49152, px, nullptr, nullptr, 128, 128);
        k_gemm<2,2,4><<<gF, 256, SMEMB>>>(px, nullptr, nullptr, g2 + l * Dc, b2 + l * Dc,
                                          lwh + 65536, lwl + 65536, nullptr, fhi, flo, 128, 512);
        k_gemm<0,1,2><<<gD32, 256, SMEMB>>>(nullptr, fhi, flo, nullptr, nullptr,
                                            lwh + 131072, lwl + 131072, px, nullptr, nullptr, 512, 128);
    }

    k_out<<<(ROWS + 7) / 8, 256>>>(fc_w, fc_b, out);
}

// round 15
// speedup vs baseline: 1.4265x; 1.1577x over previous
#include <cuda_runtime.h>
#include <cuda_bf16.h>
#include <math.h>

#define Bc      8
#define Nc      1024
#define Mc      512
#define Dc      128
#define Lc      6
#define DFFc    512
#define Sc      1536
#define HDc     16
#define MAXNB   64
#define ROWS    12288
#define HROWS   6144          // rows per stream half (4 batches)
#define PER_L   196608

// ---------------- scratch ------------------------------------------------------
__device__ float g_x  [ROWS * Dc];
__device__ float g_qkv[ROWS * 384];
__device__ float g_te [Bc * Dc];
__device__ float g_nodes[ROWS];
__device__ int   g_adj[Sc * MAXNB];
__device__ int   g_adjcnt[Sc];

__device__ __nv_bfloat16 g_wThi[Lc * PER_L];
__device__ __nv_bfloat16 g_wTlo[Lc * PER_L];
__device__ __nv_bfloat16 g_ohi[ROWS * Dc];
__device__ __nv_bfloat16 g_olo[ROWS * Dc];
__device__ __nv_bfloat16 g_fhi[ROWS * DFFc];
__device__ __nv_bfloat16 g_flo[ROWS * DFFc];

__device__ __forceinline__ void split_bf16(float v, __nv_bfloat16& hi, __nv_bfloat16& lo) {
    hi = __float2bfloat16_rn(v);
    lo = __float2bfloat16_rn(v - __bfloat162float(hi));
}
__device__ __forceinline__ unsigned pack2hi(float a, float b) {
    __nv_bfloat162 p; p.x = __float2bfloat16_rn(a); p.y = __float2bfloat16_rn(b);
    return *(unsigned*)&p;
}
__device__ __forceinline__ unsigned pack2lo(float a, float b) {
    __nv_bfloat162 p;
    p.x = __float2bfloat16_rn(a - __bfloat162float(__float2bfloat16_rn(a)));
    p.y = __float2bfloat16_rn(b - __bfloat162float(__float2bfloat16_rn(b)));
    return *(unsigned*)&p;
}

// ---------------- cp.async helpers ----------------------------------------------
__device__ __forceinline__ void cp16(unsigned dst, const void* src) {
    asm volatile("cp.async.cg.shared.global [%0], [%1], 16;" :: "r"(dst), "l"(src));
}
__device__ __forceinline__ void cp_commit() { asm volatile("cp.async.commit_group;"); }
__device__ __forceinline__ void cp_wait0()  { asm volatile("cp.async.wait_group 0;" ::: "memory"); }

// ---------------- merged init: te + syndrome nodes + adjacency ------------------
__global__ void k_init0(const int* __restrict__ t, const float* __restrict__ time_table,
                        const float* __restrict__ r_t, const int* __restrict__ pcm) {
    int blk = blockIdx.x;
    int lane = threadIdx.x & 31;
    if (blk < 512) {
        int w = blk * 8 + (threadIdx.x >> 5);
        int b = w >> 9, m = w & 511;
        int cnt = 0;
        #pragma unroll
        for (int i = 0; i < 32; i++) {
            int col = lane + i * 32;
            bool pred = (pcm[(size_t)m * Nc + col] != 0) && (r_t[(size_t)b * Nc + col] < 0.0f);
            cnt += __popc(__ballot_sync(0xffffffffu, pred));
        }
        if (lane == 0) g_nodes[(size_t)b * Sc + Nc + m] = (float)(cnt & 1);
    } else if (blk < 704) {
        int s = (blk - 512) * 8 + (threadIdx.x >> 5);
        unsigned lt = (1u << lane) - 1u;
        int* adj = g_adj + s * MAXNB;
        int cnt = 1;
        if (lane == 0) adj[0] = s;
        if (s < Nc) {
            #pragma unroll
            for (int i = 0; i < 16; i++) {
                int m = lane + i * 32;
                bool pred = pcm[(size_t)m * Nc + s] != 0;
                unsigned bal = __ballot_sync(0xffffffffu, pred);
                int rank = __popc(bal & lt);
                if (pred && cnt + rank < MAXNB) adj[cnt + rank] = Nc + m;
                cnt += __popc(bal);
            }
        } else {
            const int* row = pcm + (size_t)(s - Nc) * Nc;
            #pragma unroll
            for (int i = 0; i < 32; i++) {
                int n = lane + i * 32;
                bool pred = row[n] != 0;
                unsigned bal = __ballot_sync(0xffffffffu, pred);
                int rank = __popc(bal & lt);
                if (pred && cnt + rank < MAXNB) adj[cnt + rank] = n;
                cnt += __popc(bal);
            }
        }
        if (lane == 0) g_adjcnt[s] = cnt < MAXNB ? cnt : MAXNB;
    } else {
        #pragma unroll
        for (int i = threadIdx.x; i < Bc * Dc; i += 256) {
            int b = i >> 7, d = i & 127;
            g_te[i] = time_table[t[b] * Dc + d];
        }
    }
}

__global__ void k_xinit(const float* __restrict__ src_embed, const float* __restrict__ r_t) {
    int i = blockIdx.x * blockDim.x + threadIdx.x;
    if (i >= ROWS * Dc) return;
    int d = i & 127;
    int bs = i >> 7;
    int b = bs / Sc, s = bs % Sc;
    float node = (s < Nc) ? fabsf(r_t[(size_t)b * Nc + s]) : g_nodes[bs];
    g_x[i] = src_embed[s * Dc + d] * node * g_te[b * Dc + d];
}

// ---------------- weight transpose+split ----------------------------------------
__global__ void k_wsplit(const float* __restrict__ Wq, const float* __restrict__ Wk,
                         const float* __restrict__ Wv, const float* __restrict__ Wo,
                         const float* __restrict__ W1, const float* __restrict__ W2) {
    __shared__ float s[32][33];
    int bid = blockIdx.x;
    int l = bid / 192, tt = bid % 192;
    const float* src; int Nn, k0, n0; size_t dstBase; int dstLd;
    if (tt < 64) {
        int seg = tt >> 4, local = tt & 15;
        k0 = (local >> 2) * 32; n0 = (local & 3) * 32; Nn = 128; dstLd = 128;
        if      (seg == 0) { src = Wq + (size_t)l * 16384; dstBase = (size_t)l * PER_L; }
        else if (seg == 1) { src = Wk + (size_t)l * 16384; dstBase = (size_t)l * PER_L + 16384; }
        else if (seg == 2) { src = Wv + (size_t)l * 16384; dstBase = (size_t)l * PER_L + 32768; }
        else               { src = Wo + (size_t)l * 16384; dstBase = (size_t)l * PER_L + 49152; }
    } else if (tt < 128) {
        int local = tt - 64;
        k0 = (local >> 4) * 32; n0 = (local & 15) * 32; Nn = 512; dstLd = 128;
        src = W1 + (size_t)l * 65536; dstBase = (size_t)l * PER_L + 65536;
    } else {
        int local = tt - 128;
        k0 = (local >> 2) * 32; n0 = (local & 3) * 32; Nn = 128; dstLd = 512;
        src = W2 + (size_t)l * 65536; dstBase = (size_t)l * PER_L + 131072;
    }
    int tx = threadIdx.x & 31, ty = threadIdx.x >> 5;
    #pragma unroll
    for (int j = 0; j < 4; j++)
        s[ty + j * 8][tx] = src[(size_t)(k0 + ty + j * 8) * Nn + n0 + tx];
    __syncthreads();
    #pragma unroll
    for (int j = 0; j < 4; j++) {
        int n = n0 + ty + j * 8;
        float v = s[tx][ty + j * 8];
        __nv_bfloat16 hi, lo;
        split_bf16(v, hi, lo);
        size_t o = dstBase + (size_t)n * dstLd + k0 + tx;
        g_wThi[o] = hi;
        g_wTlo[o] = lo;
    }
}

// ---------------- fused LN + bf16x3 GEMM, ldmatrix + cp.async --------------------
#define SW 68
#define A_WORDS (128 * SW)
#define B_WORDS (64 * SW)
#define SMEMB ((2 * A_WORDS + 2 * B_WORDS) * 4)
#define ROWS16B (16 * SW * 4)

__device__ __forceinline__ void mma_bf16(float* c, const unsigned* a, const unsigned* b) {
    asm volatile(
        "mma.sync.aligned.m16n8k16.row.col.f32.bf16.bf16.f32 "
        "{%0,%1,%2,%3}, {%4,%5,%6,%7}, {%8,%9}, {%0,%1,%2,%3};"
        : "+f"(c[0]), "+f"(c[1]), "+f"(c[2]), "+f"(c[3])
        : "r"(a[0]), "r"(a[1]), "r"(a[2]), "r"(a[3]), "r"(b[0]), "r"(b[1]));
}
__device__ __forceinline__ void ldsm4(unsigned* d, unsigned addr) {
    asm volatile("ldmatrix.sync.aligned.m8n8.x4.shared.b16 {%0,%1,%2,%3}, [%4];"
                 : "=r"(d[0]), "=r"(d[1]), "=r"(d[2]), "=r"(d[3]) : "r"(addr));
}

template <int AMODE, int EPI, int NT>   // BN = 16*NT
__global__ void __launch_bounds__(256, 2)
k_gemm(int rowOff,
       const float* __restrict__ Xf,
       const __nv_bfloat16* __restrict__ Ahi, const __nv_bfloat16* __restrict__ Alo,
       const float* __restrict__ gg, const float* __restrict__ bb,
       const __nv_bfloat16* __restrict__ Bhi, const __nv_bfloat16* __restrict__ Blo,
       float* __restrict__ C, __nv_bfloat16* __restrict__ Chi, __nv_bfloat16* __restrict__ Clo,
       int K, int Nn) {
    extern __shared__ unsigned smw[];
    unsigned* sAhi = smw;
    unsigned* sAlo = sAhi + A_WORDS;
    unsigned* sBhi = sAlo + A_WORDS;
    unsigned* sBlo = sBhi + B_WORDS;

    const int tid = threadIdx.x;
    const int lane = tid & 31, warp = tid >> 5;
    const int wm = (warp >> 1) * 32, wn = (warp & 1) * (NT * 8);
    const int g = lane >> 2, q4 = lane & 3;
    const int BN = 16 * NT;
    const int rowBase = rowOff + blockIdx.y * 128, colBase = blockIdx.x * BN;

    const unsigned sAhiAddr = (unsigned)__cvta_generic_to_shared(sAhi);
    const unsigned sAloAddr = (unsigned)__cvta_generic_to_shared(sAlo);
    const unsigned sBhiAddr = (unsigned)__cvta_generic_to_shared(sBhi);
    const unsigned sBloAddr = (unsigned)__cvta_generic_to_shared(sBlo);

    const unsigned aOff = (unsigned)((wm + (lane & 15)) * SW + (lane >> 4) * 4) * 4u;
    const unsigned bOff = (unsigned)((wn + ((lane >> 4) & 1) * 8 + (lane & 7)) * SW
                                     + ((lane >> 3) & 1) * 4) * 4u;
    const unsigned aHiBase = sAhiAddr + aOff;
    const unsigned aLoBase = sAloAddr + aOff;
    const unsigned bHiBase = sBhiAddr + bOff;
    const unsigned bLoBase = sBloAddr + bOff;

    float acc[2][NT][4];
    #pragma unroll
    for (int mt = 0; mt < 2; mt++)
        #pragma unroll
        for (int nt = 0; nt < NT; nt++)
            #pragma unroll
            for (int i = 0; i < 4; i++) acc[mt][nt][i] = 0.0f;

    float4 gv, bv, tv;
    if (AMODE != 0) {
        gv = *(const float4*)&gg[lane * 4];
        bv = *(const float4*)&bb[lane * 4];
        if (AMODE == 2) {
            int bIdx = rowBase / Sc;
            tv = *(const float4*)&g_te[bIdx * Dc + lane * 4];
        }
    }

    for (int kt = 0; kt < K; kt += 128) {
        if (kt) __syncthreads();

        // ---- B slice via cp.async, issued FIRST ----
        #pragma unroll
        for (int i = 0; i < NT; i++) {
            int t = tid + i * 256;
            int n = t >> 4, c = t & 15;
            size_t goff = (size_t)(colBase + n) * K + kt + c * 8;
            unsigned sm = (unsigned)(n * SW + c * 4) * 4u;
            cp16(sBhiAddr + sm, Bhi + goff);
            cp16(sBloAddr + sm, Blo + goff);
        }

        if (AMODE == 0) {
            #pragma unroll
            for (int i = 0; i < 8; i++) {
                int t = tid + i * 256;
                int r = t >> 4, c = t & 15;
                size_t goff = (size_t)(rowBase + r) * K + kt + c * 8;
                unsigned sm = (unsigned)(r * SW + c * 4) * 4u;
                cp16(sAhiAddr + sm, Ahi + goff);
                cp16(sAloAddr + sm, Alo + goff);
            }
            cp_commit();
            cp_wait0();
        } else {
            cp_commit();
            #pragma unroll
            for (int p = 0; p < 16; p++) {
                int r = warp * 16 + p;
                float4 xv = *(const float4*)&Xf[(size_t)(rowBase + r) * 128 + lane * 4];
                float s1 = xv.x + xv.y + xv.z + xv.w;
                float s2 = xv.x * xv.x + xv.y * xv.y + xv.z * xv.z + xv.w * xv.w;
                #pragma unroll
                for (int o = 16; o > 0; o >>= 1) {
                    s1 += __shfl_xor_sync(0xffffffffu, s1, o);
                    s2 += __shfl_xor_sync(0xffffffffu, s2, o);
                }
                float mean = s1 * (1.0f / 128.0f);
                float var  = s2 * (1.0f / 128.0f) - mean * mean;
                float inv  = rsqrtf(var + 1e-5f);
                float o0 = (xv.x - mean) * inv * gv.x + bv.x;
                float o1 = (xv.y - mean) * inv * gv.y + bv.y;
                float o2 = (xv.z - mean) * inv * gv.z + bv.z;
                float o3 = (xv.w - mean) * inv * gv.w + bv.w;
                if (AMODE == 2) { o0 *= tv.x; o1 *= tv.y; o2 *= tv.z; o3 *= tv.w; }
                sAhi[r * SW + lane * 2]     = pack2hi(o0, o1);
                sAhi[r * SW + lane * 2 + 1] = pack2hi(o2, o3);
                sAlo[r * SW + lane * 2]     = pack2lo(o0, o1);
                sAlo[r * SW + lane * 2 + 1] = pack2lo(o2, o3);
            }
            cp_wait0();
        }
        __syncthreads();

        #pragma unroll
        for (int ks = 0; ks < 8; ks++) {
            const unsigned ko = ks * 32u;
            unsigned ah[2][4], al[2][4], bh[NT][2], bl[NT][2];
            #pragma unroll
            for (int mt = 0; mt < 2; mt++) {
                ldsm4(ah[mt], aHiBase + mt * ROWS16B + ko);
                ldsm4(al[mt], aLoBase + mt * ROWS16B + ko);
            }
            #pragma unroll
            for (int pr = 0; pr < NT / 2; pr++) {
                unsigned t0[4], t1[4];
                ldsm4(t0, bHiBase + pr * ROWS16B + ko);
                ldsm4(t1, bLoBase + pr * ROWS16B + ko);
                bh[pr * 2][0] = t0[0]; bh[pr * 2][1] = t0[1];
                bh[pr * 2 + 1][0] = t0[2]; bh[pr * 2 + 1][1] = t0[3];
                bl[pr * 2][0] = t1[0]; bl[pr * 2][1] = t1[1];
                bl[pr * 2 + 1][0] = t1[2]; bl[pr * 2 + 1][1] = t1[3];
            }
            #pragma unroll
            for (int mt = 0; mt < 2; mt++)
                #pragma unroll
                for (int nt = 0; nt < NT; nt++) {
                    mma_bf16(acc[mt][nt], ah[mt], bh[nt]);
                    mma_bf16(acc[mt][nt], ah[mt], bl[nt]);
                    mma_bf16(acc[mt][nt], al[mt], bh[nt]);
                }
        }
    }

    // ---- epilogue ----
    #pragma unroll
    for (int mt = 0; mt < 2; mt++)
        #pragma unroll
        for (int nt = 0; nt < NT; nt++) {
            int r = rowBase + wm + mt * 16 + g;
            int c = colBase + wn + nt * 8 + q4 * 2;
            float* a = acc[mt][nt];
            if (EPI == 0) {
                *(float2*)&C[(size_t)r * Nn + c]       = make_float2(a[0], a[1]);
                *(float2*)&C[(size_t)(r + 8) * Nn + c] = make_float2(a[2], a[3]);
            } else if (EPI == 1) {
                float2 v0 = *(const float2*)&C[(size_t)r * Nn + c];
                float2 v1 = *(const float2*)&C[(size_t)(r + 8) * Nn + c];
                v0.x += a[0]; v0.y += a[1]; v1.x += a[2]; v1.y += a[3];
                *(float2*)&C[(size_t)r * Nn + c]       = v0;
                *(float2*)&C[(size_t)(r + 8) * Nn + c] = v1;
            } else {
                #pragma unroll
                for (int rr = 0; rr < 2; rr++) {
                    float v0 = fmaxf(a[rr * 2 + 0], 0.0f);
                    float v1 = fmaxf(a[rr * 2 + 1], 0.0f);
                    size_t o = (size_t)(r + rr * 8) * Nn + c;
                    *(unsigned*)&Chi[o] = pack2hi(v0, v1);
                    *(unsigned*)&Clo[o] = pack2lo(v0, v1);
                }
            }
        }
}

// ---------------- sparse attention: warp per row, online softmax -----------------
__global__ void __launch_bounds__(256)
k_attn(int rowOff, const float* __restrict__ qkv,
       __nv_bfloat16* __restrict__ ohi, __nv_bfloat16* __restrict__ olo) {
    int warp = threadIdx.x >> 5, lane = threadIdx.x & 31;
    int bs = rowOff + blockIdx.x * 8 + warp;
    int b = bs / Sc, s = bs % Sc;
    int cnt = g_adjcnt[s];
    const int* adj = g_adj + s * MAXNB;

    float4 qv = *(const float4*)&qkv[(size_t)bs * 384 + lane * 4];

    float m = -1e30f, l = 0.0f;
    float4 acc = make_float4(0.0f, 0.0f, 0.0f, 0.0f);

    for (int j = 0; j < cnt; j++) {
        int n = adj[j];
        const float* kr = qkv + ((size_t)b * Sc + n) * 384 + 128;
        float4 kv = *(const float4*)&kr[lane * 4];
        float d = qv.x * kv.x + qv.y * kv.y + qv.z * kv.z + qv.w * kv.w;
        d += __shfl_xor_sync(0xffffffffu, d, 1);
        d += __shfl_xor_sync(0xffffffffu, d, 2);
        float sc = d * 0.25f;
        float mn = fmaxf(m, sc);
        float scale = __expf(m - mn);
        float p = __expf(sc - mn);
        l = l * scale + p;
        float4 vv = *(const float4*)&kr[128 + lane * 4];
        acc.x = acc.x * scale + p * vv.x;
        acc.y = acc.y * scale + p * vv.y;
        acc.z = acc.z * scale + p * vv.z;
        acc.w = acc.w * scale + p * vv.w;
        m = mn;
    }

    float inv = 1.0f / l;
    float v0 = acc.x * inv, v1 = acc.y * inv, v2 = acc.z * inv, v3 = acc.w * inv;
    size_t o = (size_t)bs * Dc + lane * 4;
    *(unsigned*)&ohi[o]     = pack2hi(v0, v1);
    *(unsigned*)&ohi[o + 2] = pack2hi(v2, v3);
    *(unsigned*)&olo[o]     = pack2lo(v0, v1);
    *(unsigned*)&olo[o + 2] = pack2lo(v2, v3);
}

// ---------------- final projection -----------------------------------------------
__global__ void k_out(const float* __restrict__ fc_w, const float* __restrict__ fc_b,
                      float* __restrict__ out) {
    int row = blockIdx.x * 8 + (threadIdx.x >> 5);
    if (row >= ROWS) return;
    int lane = threadIdx.x & 31;
    float sum = 0.0f;
    #pragma unroll
    for (int d = lane; d < Dc; d += 32) sum += g_x[(size_t)row * Dc + d] * fc_w[d];
    #pragma unroll
    for (int off = 16; off > 0; off >>= 1) sum += __shfl_xor_sync(0xffffffffu, sum, off);
    if (lane == 0) out[row] = sum + fc_b[0];
}

// ---------------- launcher ---------------------------------------------------------
extern "C" void kernel_launch(void* const* d_in, const int* in_sizes, int n_in,
                              void* d_out, int out_size) {
    const float* r_t        = (const float*)d_in[0];
    const int*   t          = (const int*)  d_in[1];
    const int*   pcm        = (const int*)  d_in[2];
    const float* src_embed  = (const float*)d_in[4];
    const float* time_table = (const float*)d_in[5];
    const float* Wq = (const float*)d_in[6];
    const float* Wk = (const float*)d_in[7];
    const float* Wv = (const float*)d_in[8];
    const float* Wo = (const float*)d_in[9];
    const float* W1 = (const float*)d_in[10];
    const float* W2 = (const float*)d_in[11];
    const float* g1 = (const float*)d_in[12];
    const float* b1 = (const float*)d_in[13];
    const float* g2 = (const float*)d_in[14];
    const float* b2 = (const float*)d_in[15];
    const float* fc_w = (const float*)d_in[16];
    const float* fc_b = (const float*)d_in[17];
    float* out = (float*)d_out;

    float *px, *pqkv;
    __nv_bfloat16 *whi, *wlo, *ohi, *olo, *fhi, *flo;
    cudaGetSymbolAddress((void**)&px,   g_x);
    cudaGetSymbolAddress((void**)&pqkv, g_qkv);
    cudaGetSymbolAddress((void**)&whi,  g_wThi);
    cudaGetSymbolAddress((void**)&wlo,  g_wTlo);
    cudaGetSymbolAddress((void**)&ohi,  g_ohi);
    cudaGetSymbolAddress((void**)&olo,  g_olo);
    cudaGetSymbolAddress((void**)&fhi,  g_fhi);
    cudaGetSymbolAddress((void**)&flo,  g_flo);

    static cudaStream_t sA = nullptr, sB = nullptr;
    static cudaEvent_t ev0, evW, evI, evA, evB;
    static int inited = 0;
    if (!inited) {
        cudaFuncSetAttribute(k_gemm<1,0,4>, cudaFuncAttributeMaxDynamicSharedMemorySize, SMEMB);
        cudaFuncSetAttribute(k_gemm<0,1,2>, cudaFuncAttributeMaxDynamicSharedMemorySize, SMEMB);
        cudaFuncSetAttribute(k_gemm<2,2,4>, cudaFuncAttributeMaxDynamicSharedMemorySize, SMEMB);
        cudaFuncSetAttribute(k_gemm<1,0,4>, cudaFuncAttributePreferredSharedMemoryCarveout, 100);
        cudaFuncSetAttribute(k_gemm<0,1,2>, cudaFuncAttributePreferredSharedMemoryCarveout, 100);
        cudaFuncSetAttribute(k_gemm<2,2,4>, cudaFuncAttributePreferredSharedMemoryCarveout, 100);
        cudaStreamCreateWithFlags(&sA, cudaStreamNonBlocking);
        cudaStreamCreateWithFlags(&sB, cudaStreamNonBlocking);
        cudaEventCreateWithFlags(&ev0, cudaEventDisableTiming);
        cudaEventCreateWithFlags(&evW, cudaEventDisableTiming);
        cudaEventCreateWithFlags(&evI, cudaEventDisableTiming);
        cudaEventCreateWithFlags(&evA, cudaEventDisableTiming);
        cudaEventCreateWithFlags(&evB, cudaEventDisableTiming);
        inited = 1;
    }

    // ---- fork: wsplit on sA, node/adj/te + xinit on default stream ----
    cudaEventRecord(ev0, 0);
    cudaStreamWaitEvent(sA, ev0, 0);
    k_wsplit<<<Lc * 192, 256, 0, sA>>>(Wq, Wk, Wv, Wo, W1, W2);
    cudaEventRecord(evW, sA);

    k_init0<<<705, 256>>>(t, time_table, r_t, pcm);
    k_xinit<<<(ROWS * Dc + 255) / 256, 256>>>(src_embed, r_t);
    cudaEventRecord(evI, 0);

    // both layer streams need weights + x ready
    cudaStreamWaitEvent(sA, evI, 0);
    cudaStreamWaitEvent(sB, evI, 0);
    cudaStreamWaitEvent(sB, evW, 0);

    dim3 gQKV(6, 48);    // per-half: 288 CTAs
    dim3 gD32(4, 48);    // 192
    dim3 gF  (8, 48);    // 384

    for (int l = 0; l < Lc; l++) {
        const __nv_bfloat16* lwh = whi + (size_t)l * PER_L;
        const __nv_bfloat16* lwl = wlo + (size_t)l * PER_L;

        // ---- half A (rows 0..6143) ----
        k_gemm<1,0,4><<<gQKV, 256, SMEMB, sA>>>(0, px, nullptr, nullptr, g1 + l * Dc, b1 + l * Dc,
                                                lwh, lwl, pqkv, nullptr, nullptr, 128, 384);
        k_attn<<<HROWS / 8, 256, 0, sA>>>(0, pqkv, ohi, olo);
        k_gemm<0,1,2><<<gD32, 256, SMEMB, sA>>>(0, nullptr, ohi, olo, nullptr, nullptr,
                                                lwh + 49152, lwl + 49152, px, nullptr, nullptr, 128, 128);
        k_gemm<2,2,4><<<gF, 256, SMEMB, sA>>>(0, px, nullptr, nullptr, g2 + l * Dc, b2 + l * Dc,
                                              lwh + 65536, lwl + 65536, nullptr, fhi, flo, 128, 512);
        k_gemm<0,1,2><<<gD32, 256, SMEMB, sA>>>(0, nullptr, fhi, flo, nullptr, nullptr,
                                                lwh + 131072, lwl + 131072, px, nullptr, nullptr, 512, 128);

        // ---- half B (rows 6144..12287) ----
        k_gemm<1,0,4><<<gQKV, 256, SMEMB, sB>>>(HROWS, px, nullptr, nullptr, g1 + l * Dc, b1 + l * Dc,
                                                lwh, lwl, pqkv, nullptr, nullptr, 128, 384);
        k_attn<<<HROWS / 8, 256, 0, sB>>>(HROWS, pqkv, ohi, olo);
        k_gemm<0,1,2><<<gD32, 256, SMEMB, sB>>>(HROWS, nullptr, ohi, olo, nullptr, nullptr,
                                                lwh + 49152, lwl + 49152, px, nullptr, nullptr, 128, 128);
        k_gemm<2,2,4><<<gF, 256, SMEMB, sB>>>(HROWS, px, nullptr, nullptr, g2 + l * Dc, b2 + l * Dc,
                                              lwh + 65536, lwl + 65536, nullptr, fhi, flo, 128, 512);
        k_gemm<0,1,2><<<gD32, 256, SMEMB, sB>>>(HROWS, nullptr, fhi, flo, nullptr, nullptr,
                                                lwh + 131072, lwl + 131072, px, nullptr, nullptr, 512, 128);
    }

    // ---- join ----
    cudaEventRecord(evA, sA);
    cudaEventRecord(evB, sB);
    cudaStreamWaitEvent(0, evA, 0);
    cudaStreamWaitEvent(0, evB, 0);

    k_out<<<(ROWS + 7) / 8, 256>>>(fc_w, fc_b, out);
}

// round 17
// speedup vs baseline: 1.4494x; 1.0161x over previous
#include <cuda_runtime.h>
#include <cuda_bf16.h>
#include <math.h>

#define Bc      8
#define Nc      1024
#define Mc      512
#define Dc      128
#define Lc      6
#define DFFc    512
#define Sc      1536
#define HDc     16
#define MAXNB   64
#define ROWS    12288
#define HROWS   6144
#define PER_L   196608

// ---------------- scratch ------------------------------------------------------
__device__ float g_x  [ROWS * Dc];
__device__ float g_qkv[ROWS * 384];
__device__ float g_te [Bc * Dc];
__device__ float g_nodes[ROWS];
__device__ int   g_adj[Sc * MAXNB];
__device__ int   g_adjcnt[Sc];

__device__ __nv_bfloat16 g_wThi[Lc * PER_L];
__device__ __nv_bfloat16 g_wTlo[Lc * PER_L];
__device__ __nv_bfloat16 g_ohi[ROWS * Dc];
__device__ __nv_bfloat16 g_olo[ROWS * Dc];
__device__ __nv_bfloat16 g_fhi[ROWS * DFFc];
__device__ __nv_bfloat16 g_flo[ROWS * DFFc];

__device__ __forceinline__ void split_bf16(float v, __nv_bfloat16& hi, __nv_bfloat16& lo) {
    hi = __float2bfloat16_rn(v);
    lo = __float2bfloat16_rn(v - __bfloat162float(hi));
}
__device__ __forceinline__ unsigned pack2hi(float a, float b) {
    __nv_bfloat162 p; p.x = __float2bfloat16_rn(a); p.y = __float2bfloat16_rn(b);
    return *(unsigned*)&p;
}
__device__ __forceinline__ unsigned pack2lo(float a, float b) {
    __nv_bfloat162 p;
    p.x = __float2bfloat16_rn(a - __bfloat162float(__float2bfloat16_rn(a)));
    p.y = __float2bfloat16_rn(b - __bfloat162float(__float2bfloat16_rn(b)));
    return *(unsigned*)&p;
}

// ---------------- cp.async helpers ----------------------------------------------
__device__ __forceinline__ void cp16(unsigned dst, const void* src) {
    asm volatile("cp.async.cg.shared.global [%0], [%1], 16;" :: "r"(dst), "l"(src));
}
__device__ __forceinline__ void cp_commit() { asm volatile("cp.async.commit_group;"); }
__device__ __forceinline__ void cp_wait0()  { asm volatile("cp.async.wait_group 0;" ::: "memory"); }

// ---------------- merged init ----------------------------------------------------
__global__ void k_init0(const int* __restrict__ t, const float* __restrict__ time_table,
                        const float* __restrict__ r_t, const int* __restrict__ pcm) {
    int blk = blockIdx.x;
    int lane = threadIdx.x & 31;
    if (blk < 512) {
        int w = blk * 8 + (threadIdx.x >> 5);
        int b = w >> 9, m = w & 511;
        int cnt = 0;
        #pragma unroll
        for (int i = 0; i < 32; i++) {
            int col = lane + i * 32;
            bool pred = (pcm[(size_t)m * Nc + col] != 0) && (r_t[(size_t)b * Nc + col] < 0.0f);
            cnt += __popc(__ballot_sync(0xffffffffu, pred));
        }
        if (lane == 0) g_nodes[(size_t)b * Sc + Nc + m] = (float)(cnt & 1);
    } else if (blk < 704) {
        int s = (blk - 512) * 8 + (threadIdx.x >> 5);
        unsigned lt = (1u << lane) - 1u;
        int* adj = g_adj + s * MAXNB;
        int cnt = 1;
        if (lane == 0) adj[0] = s;
        if (s < Nc) {
            #pragma unroll
            for (int i = 0; i < 16; i++) {
                int m = lane + i * 32;
                bool pred = pcm[(size_t)m * Nc + s] != 0;
                unsigned bal = __ballot_sync(0xffffffffu, pred);
                int rank = __popc(bal & lt);
                if (pred && cnt + rank < MAXNB) adj[cnt + rank] = Nc + m;
                cnt += __popc(bal);
            }
        } else {
            const int* row = pcm + (size_t)(s - Nc) * Nc;
            #pragma unroll
            for (int i = 0; i < 32; i++) {
                int n = lane + i * 32;
                bool pred = row[n] != 0;
                unsigned bal = __ballot_sync(0xffffffffu, pred);
                int rank = __popc(bal & lt);
                if (pred && cnt + rank < MAXNB) adj[cnt + rank] = n;
                cnt += __popc(bal);
            }
        }
        if (lane == 0) g_adjcnt[s] = cnt < MAXNB ? cnt : MAXNB;
    } else {
        #pragma unroll
        for (int i = threadIdx.x; i < Bc * Dc; i += 256) {
            int b = i >> 7, d = i & 127;
            g_te[i] = time_table[t[b] * Dc + d];
        }
    }
}

__global__ void k_xinit(const float* __restrict__ src_embed, const float* __restrict__ r_t) {
    int i = blockIdx.x * blockDim.x + threadIdx.x;
    if (i >= ROWS * Dc) return;
    int d = i & 127;
    int bs = i >> 7;
    int b = bs / Sc, s = bs % Sc;
    float node = (s < Nc) ? fabsf(r_t[(size_t)b * Nc + s]) : g_nodes[bs];
    g_x[i] = src_embed[s * Dc + d] * node * g_te[b * Dc + d];
}

// ---------------- weight transpose+split ----------------------------------------
__global__ void k_wsplit(const float* __restrict__ Wq, const float* __restrict__ Wk,
                         const float* __restrict__ Wv, const float* __restrict__ Wo,
                         const float* __restrict__ W1, const float* __restrict__ W2) {
    __shared__ float s[32][33];
    int bid = blockIdx.x;
    int l = bid / 192, tt = bid % 192;
    const float* src; int Nn, k0, n0; size_t dstBase; int dstLd;
    if (tt < 64) {
        int seg = tt >> 4, local = tt & 15;
        k0 = (local >> 2) * 32; n0 = (local & 3) * 32; Nn = 128; dstLd = 128;
        if      (seg == 0) { src = Wq + (size_t)l * 16384; dstBase = (size_t)l * PER_L; }
        else if (seg == 1) { src = Wk + (size_t)l * 16384; dstBase = (size_t)l * PER_L + 16384; }
        else if (seg == 2) { src = Wv + (size_t)l * 16384; dstBase = (size_t)l * PER_L + 32768; }
        else               { src = Wo + (size_t)l * 16384; dstBase = (size_t)l * PER_L + 49152; }
    } else if (tt < 128) {
        int local = tt - 64;
        k0 = (local >> 4) * 32; n0 = (local & 15) * 32; Nn = 512; dstLd = 128;
        src = W1 + (size_t)l * 65536; dstBase = (size_t)l * PER_L + 65536;
    } else {
        int local = tt - 128;
        k0 = (local >> 2) * 32; n0 = (local & 3) * 32; Nn = 128; dstLd = 512;
        src = W2 + (size_t)l * 65536; dstBase = (size_t)l * PER_L + 131072;
    }
    int tx = threadIdx.x & 31, ty = threadIdx.x >> 5;
    #pragma unroll
    for (int j = 0; j < 4; j++)
        s[ty + j * 8][tx] = src[(size_t)(k0 + ty + j * 8) * Nn + n0 + tx];
    __syncthreads();
    #pragma unroll
    for (int j = 0; j < 4; j++) {
        int n = n0 + ty + j * 8;
        float v = s[tx][ty + j * 8];
        __nv_bfloat16 hi, lo;
        split_bf16(v, hi, lo);
        size_t o = dstBase + (size_t)n * dstLd + k0 + tx;
        g_wThi[o] = hi;
        g_wTlo[o] = lo;
    }
}

// ---------------- fused LN + bf16x3 GEMM -----------------------------------------
#define SW 68
#define A_WORDS (128 * SW)
#define B_WORDS (64 * SW)
#define SMEMB ((2 * A_WORDS + 2 * B_WORDS) * 4)
#define ROWS16B (16 * SW * 4)

__device__ __forceinline__ void mma_bf16(float* c, const unsigned* a, const unsigned* b) {
    asm volatile(
        "mma.sync.aligned.m16n8k16.row.col.f32.bf16.bf16.f32 "
        "{%0,%1,%2,%3}, {%4,%5,%6,%7}, {%8,%9}, {%0,%1,%2,%3};"
        : "+f"(c[0]), "+f"(c[1]), "+f"(c[2]), "+f"(c[3])
        : "r"(a[0]), "r"(a[1]), "r"(a[2]), "r"(a[3]), "r"(b[0]), "r"(b[1]));
}
__device__ __forceinline__ void ldsm4(unsigned* d, unsigned addr) {
    asm volatile("ldmatrix.sync.aligned.m8n8.x4.shared.b16 {%0,%1,%2,%3}, [%4];"
                 : "=r"(d[0]), "=r"(d[1]), "=r"(d[2]), "=r"(d[3]) : "r"(addr));
}

template <int AMODE, int EPI, int NT>   // BN = 16*NT
__global__ void __launch_bounds__(256, 2)
k_gemm(int rowOff,
       const float* __restrict__ Xf,
       const __nv_bfloat16* __restrict__ Ahi, const __nv_bfloat16* __restrict__ Alo,
       const float* __restrict__ gg, const float* __restrict__ bb,
       const __nv_bfloat16* __restrict__ Bhi, const __nv_bfloat16* __restrict__ Blo,
       float* __restrict__ C, __nv_bfloat16* __restrict__ Chi, __nv_bfloat16* __restrict__ Clo,
       int K, int Nn) {
    extern __shared__ unsigned smw[];
    unsigned* sAhi = smw;
    unsigned* sAlo = sAhi + A_WORDS;
    unsigned* sBhi = sAlo + A_WORDS;
    unsigned* sBlo = sBhi + B_WORDS;

    const int tid = threadIdx.x;
    const int lane = tid & 31, warp = tid >> 5;
    const int wm = (warp >> 1) * 32, wn = (warp & 1) * (NT * 8);
    const int g = lane >> 2, q4 = lane & 3;
    const int BN = 16 * NT;
    const int rowBase = rowOff + blockIdx.y * 128, colBase = blockIdx.x * BN;

    const unsigned sAhiAddr = (unsigned)__cvta_generic_to_shared(sAhi);
    const unsigned sAloAddr = (unsigned)__cvta_generic_to_shared(sAlo);
    const unsigned sBhiAddr = (unsigned)__cvta_generic_to_shared(sBhi);
    const unsigned sBloAddr = (unsigned)__cvta_generic_to_shared(sBlo);

    const unsigned aOff = (unsigned)((wm + (lane & 15)) * SW + (lane >> 4) * 4) * 4u;
    const unsigned bOff = (unsigned)((wn + ((lane >> 4) & 1) * 8 + (lane & 7)) * SW
                                     + ((lane >> 3) & 1) * 4) * 4u;
    const unsigned aHiBase = sAhiAddr + aOff;
    const unsigned aLoBase = sAloAddr + aOff;
    const unsigned bHiBase = sBhiAddr + bOff;
    const unsigned bLoBase = sBloAddr + bOff;

    float acc[2][NT][4];
    #pragma unroll
    for (int mt = 0; mt < 2; mt++)
        #pragma unroll
        for (int nt = 0; nt < NT; nt++)
            #pragma unroll
            for (int i = 0; i < 4; i++) acc[mt][nt][i] = 0.0f;

    float2 cpre[2 * NT * 2];   // EPI==1 residual prefetch

    float4 gv, bv, tv;
    if (AMODE != 0) {
        gv = *(const float4*)&gg[lane * 4];
        bv = *(const float4*)&bb[lane * 4];
        if (AMODE == 2) {
            int bIdx = rowBase / Sc;
            tv = *(const float4*)&g_te[bIdx * Dc + lane * 4];
        }
    }

    for (int kt = 0; kt < K; kt += 128) {
        if (kt) __syncthreads();

        // ---- B slice via cp.async, issued FIRST ----
        #pragma unroll
        for (int i = 0; i < NT; i++) {
            int t = tid + i * 256;
            int n = t >> 4, c = t & 15;
            size_t goff = (size_t)(colBase + n) * K + kt + c * 8;
            unsigned sm = (unsigned)(n * SW + c * 4) * 4u;
            cp16(sBhiAddr + sm, Bhi + goff);
            cp16(sBloAddr + sm, Blo + goff);
        }

        if (AMODE == 0) {
            #pragma unroll
            for (int i = 0; i < 8; i++) {
                int t = tid + i * 256;
                int r = t >> 4, c = t & 15;
                size_t goff = (size_t)(rowBase + r) * K + kt + c * 8;
                unsigned sm = (unsigned)(r * SW + c * 4) * 4u;
                cp16(sAhiAddr + sm, Ahi + goff);
                cp16(sAloAddr + sm, Alo + goff);
            }
            cp_commit();
            cp_wait0();
        } else {
            cp_commit();
            // fused LayerNorm, batch-4 pipelined row loads
            #pragma unroll
            for (int p0 = 0; p0 < 16; p0 += 4) {
                float4 xv[4];
                #pragma unroll
                for (int j = 0; j < 4; j++)
                    xv[j] = *(const float4*)&Xf[(size_t)(rowBase + warp * 16 + p0 + j) * 128
                                                + lane * 4];
                #pragma unroll
                for (int j = 0; j < 4; j++) {
                    int r = warp * 16 + p0 + j;
                    float s1 = xv[j].x + xv[j].y + xv[j].z + xv[j].w;
                    float s2 = xv[j].x * xv[j].x + xv[j].y * xv[j].y
                             + xv[j].z * xv[j].z + xv[j].w * xv[j].w;
                    #pragma unroll
                    for (int o = 16; o > 0; o >>= 1) {
                        s1 += __shfl_xor_sync(0xffffffffu, s1, o);
                        s2 += __shfl_xor_sync(0xffffffffu, s2, o);
                    }
                    float mean = s1 * (1.0f / 128.0f);
                    float var  = s2 * (1.0f / 128.0f) - mean * mean;
                    float inv  = rsqrtf(var + 1e-5f);
                    float o0 = (xv[j].x - mean) * inv * gv.x + bv.x;
                    float o1 = (xv[j].y - mean) * inv * gv.y + bv.y;
                    float o2 = (xv[j].z - mean) * inv * gv.z + bv.z;
                    float o3 = (xv[j].w - mean) * inv * gv.w + bv.w;
                    if (AMODE == 2) { o0 *= tv.x; o1 *= tv.y; o2 *= tv.z; o3 *= tv.w; }
                    sAhi[r * SW + lane * 2]     = pack2hi(o0, o1);
                    sAhi[r * SW + lane * 2 + 1] = pack2hi(o2, o3);
                    sAlo[r * SW + lane * 2]     = pack2lo(o0, o1);
                    sAlo[r * SW + lane * 2 + 1] = pack2lo(o2, o3);
                }
            }
            cp_wait0();
        }
        __syncthreads();

        // residual prefetch on the last k-slice: MMA chain below hides the load
        if (EPI == 1 && kt + 128 >= K) {
            #pragma unroll
            for (int mt = 0; mt < 2; mt++)
                #pragma unroll
                for (int nt = 0; nt < NT; nt++) {
                    int r = rowBase + wm + mt * 16 + g;
                    int c = colBase + wn + nt * 8 + q4 * 2;
                    cpre[(mt * NT + nt) * 2]     = *(const float2*)&C[(size_t)r * Nn + c];
                    cpre[(mt * NT + nt) * 2 + 1] = *(const float2*)&C[(size_t)(r + 8) * Nn + c];
                }
        }

        #pragma unroll
        for (int ks = 0; ks < 8; ks++) {
            const unsigned ko = ks * 32u;
            unsigned ah[2][4], al[2][4], bh[NT][2], bl[NT][2];
            #pragma unroll
            for (int mt = 0; mt < 2; mt++) {
                ldsm4(ah[mt], aHiBase + mt * ROWS16B + ko);
                ldsm4(al[mt], aLoBase + mt * ROWS16B + ko);
            }
            #pragma unroll
            for (int pr = 0; pr < NT / 2; pr++) {
                unsigned t0[4], t1[4];
                ldsm4(t0, bHiBase + pr * ROWS16B + ko);
                ldsm4(t1, bLoBase + pr * ROWS16B + ko);
                bh[pr * 2][0] = t0[0]; bh[pr * 2][1] = t0[1];
                bh[pr * 2 + 1][0] = t0[2]; bh[pr * 2 + 1][1] = t0[3];
                bl[pr * 2][0] = t1[0]; bl[pr * 2][1] = t1[1];
                bl[pr * 2 + 1][0] = t1[2]; bl[pr * 2 + 1][1] = t1[3];
            }
            #pragma unroll
            for (int mt = 0; mt < 2; mt++)
                #pragma unroll
                for (int nt = 0; nt < NT; nt++) {
                    mma_bf16(acc[mt][nt], ah[mt], bh[nt]);
                    mma_bf16(acc[mt][nt], ah[mt], bl[nt]);
                    mma_bf16(acc[mt][nt], al[mt], bh[nt]);
                }
        }
    }

    // ---- epilogue ----
    #pragma unroll
    for (int mt = 0; mt < 2; mt++)
        #pragma unroll
        for (int nt = 0; nt < NT; nt++) {
            int r = rowBase + wm + mt * 16 + g;
            int c = colBase + wn + nt * 8 + q4 * 2;
            float* a = acc[mt][nt];
            if (EPI == 0) {
                *(float2*)&C[(size_t)r * Nn + c]       = make_float2(a[0], a[1]);
                *(float2*)&C[(size_t)(r + 8) * Nn + c] = make_float2(a[2], a[3]);
            } else if (EPI == 1) {
                float2 v0 = cpre[(mt * NT + nt) * 2];
                float2 v1 = cpre[(mt * NT + nt) * 2 + 1];
                v0.x += a[0]; v0.y += a[1]; v1.x += a[2]; v1.y += a[3];
                *(float2*)&C[(size_t)r * Nn + c]       = v0;
                *(float2*)&C[(size_t)(r + 8) * Nn + c] = v1;
            } else {
                #pragma unroll
                for (int rr = 0; rr < 2; rr++) {
                    float v0 = fmaxf(a[rr * 2 + 0], 0.0f);
                    float v1 = fmaxf(a[rr * 2 + 1], 0.0f);
                    size_t o = (size_t)(r + rr * 8) * Nn + c;
                    *(unsigned*)&Chi[o] = pack2hi(v0, v1);
                    *(unsigned*)&Clo[o] = pack2lo(v0, v1);
                }
            }
        }
}

// ---------------- sparse attention -------------------------------------------------
__global__ void __launch_bounds__(256)
k_attn(int rowOff, const float* __restrict__ qkv,
       __nv_bfloat16* __restrict__ ohi, __nv_bfloat16* __restrict__ olo) {
    int warp = threadIdx.x >> 5, lane = threadIdx.x & 31;
    int bs = rowOff + blockIdx.x * 8 + warp;
    int b = bs / Sc, s = bs % Sc;
    int cnt = g_adjcnt[s];
    const int* adj = g_adj + s * MAXNB;

    float4 qv = *(const float4*)&qkv[(size_t)bs * 384 + lane * 4];

    float m = -1e30f, l = 0.0f;
    float4 acc = make_float4(0.0f, 0.0f, 0.0f, 0.0f);

    for (int j = 0; j < cnt; j++) {
        int n = adj[j];
        const float* kr = qkv + ((size_t)b * Sc + n) * 384 + 128;
        float4 kv = *(const float4*)&kr[lane * 4];
        float d = qv.x * kv.x + qv.y * kv.y + qv.z * kv.z + qv.w * kv.w;
        d += __shfl_xor_sync(0xffffffffu, d, 1);
        d += __shfl_xor_sync(0xffffffffu, d, 2);
        float sc = d * 0.25f;
        float mn = fmaxf(m, sc);
        float scale = __expf(m - mn);
        float p = __expf(sc - mn);
        l = l * scale + p;
        float4 vv = *(const float4*)&kr[128 + lane * 4];
        acc.x = acc.x * scale + p * vv.x;
        acc.y = acc.y * scale + p * vv.y;
        acc.z = acc.z * scale + p * vv.z;
        acc.w = acc.w * scale + p * vv.w;
        m = mn;
    }

    float inv = 1.0f / l;
    float v0 = acc.x * inv, v1 = acc.y * inv, v2 = acc.z * inv, v3 = acc.w * inv;
    size_t o = (size_t)bs * Dc + lane * 4;
    *(unsigned*)&ohi[o]     = pack2hi(v0, v1);
    *(unsigned*)&ohi[o + 2] = pack2hi(v2, v3);
    *(unsigned*)&olo[o]     = pack2lo(v0, v1);
    *(unsigned*)&olo[o + 2] = pack2lo(v2, v3);
}

// ---------------- final projection (per-half) --------------------------------------
__global__ void k_out(int rowOff, const float* __restrict__ fc_w, const float* __restrict__ fc_b,
                      float* __restrict__ out) {
    int row = rowOff + blockIdx.x * 8 + (threadIdx.x >> 5);
    int lane = threadIdx.x & 31;
    float sum = 0.0f;
    #pragma unroll
    for (int d = lane; d < Dc; d += 32) sum += g_x[(size_t)row * Dc + d] * fc_w[d];
    #pragma unroll
    for (int off = 16; off > 0; off >>= 1) sum += __shfl_xor_sync(0xffffffffu, sum, off);
    if (lane == 0) out[row] = sum + fc_b[0];
}

// ---------------- launcher ---------------------------------------------------------
extern "C" void kernel_launch(void* const* d_in, const int* in_sizes, int n_in,
                              void* d_out, int out_size) {
    const float* r_t        = (const float*)d_in[0];
    const int*   t          = (const int*)  d_in[1];
    const int*   pcm        = (const int*)  d_in[2];
    const float* src_embed  = (const float*)d_in[4];
    const float* time_table = (const float*)d_in[5];
    const float* Wq = (const float*)d_in[6];
    const float* Wk = (const float*)d_in[7];
    const float* Wv = (const float*)d_in[8];
    const float* Wo = (const float*)d_in[9];
    const float* W1 = (const float*)d_in[10];
    const float* W2 = (const float*)d_in[11];
    const float* g1 = (const float*)d_in[12];
    const float* b1 = (const float*)d_in[13];
    const float* g2 = (const float*)d_in[14];
    const float* b2 = (const float*)d_in[15];
    const float* fc_w = (const float*)d_in[16];
    const float* fc_b = (const float*)d_in[17];
    float* out = (float*)d_out;

    float *px, *pqkv;
    __nv_bfloat16 *whi, *wlo, *ohi, *olo, *fhi, *flo;
    cudaGetSymbolAddress((void**)&px,   g_x);
    cudaGetSymbolAddress((void**)&pqkv, g_qkv);
    cudaGetSymbolAddress((void**)&whi,  g_wThi);
    cudaGetSymbolAddress((void**)&wlo,  g_wTlo);
    cudaGetSymbolAddress((void**)&ohi,  g_ohi);
    cudaGetSymbolAddress((void**)&olo,  g_olo);
    cudaGetSymbolAddress((void**)&fhi,  g_fhi);
    cudaGetSymbolAddress((void**)&flo,  g_flo);

    static cudaStream_t sA = nullptr, sB = nullptr;
    static cudaEvent_t ev0, evW, evI, evA, evB;
    static int inited = 0;
    if (!inited) {
        cudaFuncSetAttribute(k_gemm<1,0,4>, cudaFuncAttributeMaxDynamicSharedMemorySize, SMEMB);
        cudaFuncSetAttribute(k_gemm<0,1,2>, cudaFuncAttributeMaxDynamicSharedMemorySize, SMEMB);
        cudaFuncSetAttribute(k_gemm<2,2,4>, cudaFuncAttributeMaxDynamicSharedMemorySize, SMEMB);
        cudaFuncSetAttribute(k_gemm<1,0,4>, cudaFuncAttributePreferredSharedMemoryCarveout, 100);
        cudaFuncSetAttribute(k_gemm<0,1,2>, cudaFuncAttributePreferredSharedMemoryCarveout, 100);
        cudaFuncSetAttribute(k_gemm<2,2,4>, cudaFuncAttributePreferredSharedMemoryCarveout, 100);
        cudaStreamCreateWithFlags(&sA, cudaStreamNonBlocking);
        cudaStreamCreateWithFlags(&sB, cudaStreamNonBlocking);
        cudaEventCreateWithFlags(&ev0, cudaEventDisableTiming);
        cudaEventCreateWithFlags(&evW, cudaEventDisableTiming);
        cudaEventCreateWithFlags(&evI, cudaEventDisableTiming);
        cudaEventCreateWithFlags(&evA, cudaEventDisableTiming);
        cudaEventCreateWithFlags(&evB, cudaEventDisableTiming);
        inited = 1;
    }

    // ---- fork: wsplit on sA, node/adj/te + xinit on default ----
    cudaEventRecord(ev0, 0);
    cudaStreamWaitEvent(sA, ev0, 0);
    k_wsplit<<<Lc * 192, 256, 0, sA>>>(Wq, Wk, Wv, Wo, W1, W2);
    cudaEventRecord(evW, sA);

    k_init0<<<705, 256>>>(t, time_table, r_t, pcm);
    k_xinit<<<(ROWS * Dc + 255) / 256, 256>>>(src_embed, r_t);
    cudaEventRecord(evI, 0);

    cudaStreamWaitEvent(sA, evI, 0);
    cudaStreamWaitEvent(sB, evI, 0);
    cudaStreamWaitEvent(sB, evW, 0);

    dim3 gQKV(6, 48);    // per-half: 288 CTAs
    dim3 gD32(4, 48);    // 192
    dim3 gF  (8, 48);    // 384

    for (int l = 0; l < Lc; l++) {
        const __nv_bfloat16* lwh = whi + (size_t)l * PER_L;
        const __nv_bfloat16* lwl = wlo + (size_t)l * PER_L;

        // ---- half A ----
        k_gemm<1,0,4><<<gQKV, 256, SMEMB, sA>>>(0, px, nullptr, nullptr, g1 + l * Dc, b1 + l * Dc,
                                                lwh, lwl, pqkv, nullptr, nullptr, 128, 384);
        k_attn<<<HROWS / 8, 256, 0, sA>>>(0, pqkv, ohi, olo);
        k_gemm<0,1,2><<<gD32, 256, SMEMB, sA>>>(0, nullptr, ohi, olo, nullptr, nullptr,
                                                lwh + 49152, lwl + 49152, px, nullptr, nullptr, 128, 128);
        k_gemm<2,2,4><<<gF, 256, SMEMB, sA>>>(0, px, nullptr, nullptr, g2 + l * Dc, b2 + l * Dc,
                                              lwh + 65536, lwl + 65536, nullptr, fhi, flo, 128, 512);
        k_gemm<0,1,2><<<gD32, 256, SMEMB, sA>>>(0, nullptr, fhi, flo, nullptr, nullptr,
                                                lwh + 131072, lwl + 131072, px, nullptr, nullptr, 512, 128);

        // ---- half B ----
        k_gemm<1,0,4><<<gQKV, 256, SMEMB, sB>>>(HROWS, px, nullptr, nullptr, g1 + l * Dc, b1 + l * Dc,
                                                lwh, lwl, pqkv, nullptr, nullptr, 128, 384);
        k_attn<<<HROWS / 8, 256, 0, sB>>>(HROWS, pqkv, ohi, olo);
        k_gemm<0,1,2><<<gD32, 256, SMEMB, sB>>>(HROWS, nullptr, ohi, olo, nullptr, nullptr,
                                                lwh + 49152, lwl + 49152, px, nullptr, nullptr, 128, 128);
        k_gemm<2,2,4><<<gF, 256, SMEMB, sB>>>(HROWS, px, nullptr, nullptr, g2 + l * Dc, b2 + l * Dc,
                                              lwh + 65536, lwl + 65536, nullptr, fhi, flo, 128, 512);
        k_gemm<0,1,2><<<gD32, 256, SMEMB, sB>>>(HROWS, nullptr, fhi, flo, nullptr, nullptr,
                                                lwh + 131072, lwl + 131072, px, nullptr, nullptr, 512, 128);
    }

    // per-half output heads inside each stream
    k_out<<<HROWS / 8, 256, 0, sA>>>(0, fc_w, fc_b, out);
    k_out<<<HROWS / 8, 256, 0, sB>>>(HROWS, fc_w, fc_b, out);

    // ---- join ----
    cudaEventRecord(evA, sA);
    cudaEventRecord(evB, sB);
    cudaStreamWaitEvent(0, evA, 0);
    cudaStreamWaitEvent(0, evB, 0);
}